// round 10
// baseline (speedup 1.0000x reference)
#include <cuda_runtime.h>

#define DIMN 1024
#define NH   16
#define HD   64
#define BATCH 2
#define SEQ  2048
#define NTOK (BATCH*SEQ)   // 4096

// ---------------- scratch (device globals: allocation-free) ----------------
__device__ float g_q[NTOK * DIMN];
__device__ float g_k[NTOK * DIMN];
__device__ float g_v[NTOK * DIMN];
__device__ float g_ctx[NTOK * DIMN];

typedef unsigned long long u64;

// ---------------- packed f32x2 helpers (sm_100+ PTX) ----------------
__device__ __forceinline__ u64 pack2(float x, float y) {
    u64 r; asm("mov.b64 %0, {%1,%2};" : "=l"(r) : "f"(x), "f"(y)); return r;
}
__device__ __forceinline__ void ffma2(u64 &d, u64 a, u64 b) {
    asm("fma.rn.f32x2 %0, %1, %2, %0;" : "+l"(d) : "l"(a), "l"(b));
}
__device__ __forceinline__ u64 mul2(u64 a, u64 b) {
    u64 r; asm("mul.rn.f32x2 %0, %1, %2;" : "=l"(r) : "l"(a), "l"(b)); return r;
}
__device__ __forceinline__ float2 unpack2(u64 v) {
    float lo, hi; asm("mov.b64 {%0,%1}, %2;" : "=f"(lo), "=f"(hi) : "l"(v));
    float2 r; r.x = lo; r.y = hi; return r;
}

// ============================================================================
// SGEMM body: C[M,1024] = A[M,1024] @ W^T[1024,1024] + bias  (both K-major)
// BM=BN=128, BK=16, 256 threads, 8x8 microtile, f32x2 accumulation.
// ============================================================================
__device__ __forceinline__ void gemm_body(const float* __restrict__ A,
                                          const float* __restrict__ W,
                                          const float* __restrict__ bias,
                                          float* __restrict__ C)
{
    __shared__ float As[16 * 128];
    __shared__ float Bs[16 * 128];

    const int tid = threadIdx.x;
    const int m0 = blockIdx.y * 128;
    const int n0 = blockIdx.x * 128;

    // loaders: thread handles rows (lr, lr+64) at k-offset lk..lk+3 of the tile
    const int lr = tid & 63;
    const int lk = (tid >> 6) << 2;          // 0,4,8,12
    const float* Ap  = A + (size_t)(m0 + lr) * DIMN + lk;
    const float* Ap2 = Ap + (size_t)64 * DIMN;
    const float* Wp  = W + (size_t)(n0 + lr) * DIMN + lk;
    const float* Wp2 = Wp + (size_t)64 * DIMN;

    const int tr = tid >> 4;                 // 0..15 -> rows tr*8..tr*8+7
    const int tc = tid & 15;                 // 0..15 -> cols tc*8..tc*8+7

    u64 acc[8][4];
#pragma unroll
    for (int i = 0; i < 8; i++)
#pragma unroll
        for (int j = 0; j < 4; j++) acc[i][j] = 0ull;

    for (int kt = 0; kt < DIMN; kt += 16) {
        float4 a0 = *(const float4*)(Ap  + kt);
        float4 a1 = *(const float4*)(Ap2 + kt);
        float4 b0 = *(const float4*)(Wp  + kt);
        float4 b1 = *(const float4*)(Wp2 + kt);
        __syncthreads();
        // transposed store: As[k][row] (conflict-free: consecutive lr per warp)
        As[(lk+0)*128 + lr] = a0.x;  As[(lk+1)*128 + lr] = a0.y;
        As[(lk+2)*128 + lr] = a0.z;  As[(lk+3)*128 + lr] = a0.w;
        As[(lk+0)*128 + 64 + lr] = a1.x;  As[(lk+1)*128 + 64 + lr] = a1.y;
        As[(lk+2)*128 + 64 + lr] = a1.z;  As[(lk+3)*128 + 64 + lr] = a1.w;
        Bs[(lk+0)*128 + lr] = b0.x;  Bs[(lk+1)*128 + lr] = b0.y;
        Bs[(lk+2)*128 + lr] = b0.z;  Bs[(lk+3)*128 + lr] = b0.w;
        Bs[(lk+0)*128 + 64 + lr] = b1.x;  Bs[(lk+1)*128 + 64 + lr] = b1.y;
        Bs[(lk+2)*128 + 64 + lr] = b1.z;  Bs[(lk+3)*128 + 64 + lr] = b1.w;
        __syncthreads();

#pragma unroll
        for (int k = 0; k < 16; k++) {
            float4 ra0 = *(const float4*)&As[k*128 + tr*8];
            float4 ra1 = *(const float4*)&As[k*128 + tr*8 + 4];
            ulonglong2 rb0 = *(const ulonglong2*)&Bs[k*128 + tc*8];
            ulonglong2 rb1 = *(const ulonglong2*)&Bs[k*128 + tc*8 + 4];
            const u64 bb0 = rb0.x, bb1 = rb0.y, bb2 = rb1.x, bb3 = rb1.y;
            float av[8] = {ra0.x, ra0.y, ra0.z, ra0.w, ra1.x, ra1.y, ra1.z, ra1.w};
#pragma unroll
            for (int i = 0; i < 8; i++) {
                u64 ad = pack2(av[i], av[i]);
                ffma2(acc[i][0], ad, bb0);
                ffma2(acc[i][1], ad, bb1);
                ffma2(acc[i][2], ad, bb2);
                ffma2(acc[i][3], ad, bb3);
            }
        }
    }

    // epilogue: add bias, write two float4 per row
    const float* bp = bias + n0 + tc * 8;
    float bvv[8];
#pragma unroll
    for (int j = 0; j < 8; j++) bvv[j] = bp[j];
#pragma unroll
    for (int i = 0; i < 8; i++) {
        float* Cp = C + (size_t)(m0 + tr*8 + i) * DIMN + n0 + tc*8;
        float2 v0 = unpack2(acc[i][0]);
        float2 v1 = unpack2(acc[i][1]);
        float2 v2 = unpack2(acc[i][2]);
        float2 v3 = unpack2(acc[i][3]);
        float4 o0 = make_float4(v0.x + bvv[0], v0.y + bvv[1], v1.x + bvv[2], v1.y + bvv[3]);
        float4 o1 = make_float4(v2.x + bvv[4], v2.y + bvv[5], v3.x + bvv[6], v3.y + bvv[7]);
        *(float4*)(Cp)     = o0;
        *(float4*)(Cp + 4) = o1;
    }
}

// QKV: grid.z selects projection -> better L2 reuse of x, one launch.
__global__ __launch_bounds__(256) void qkv_kernel(
    const float* __restrict__ x,
    const float* __restrict__ Wq, const float* __restrict__ bq,
    const float* __restrict__ Wk, const float* __restrict__ bk,
    const float* __restrict__ Wv, const float* __restrict__ bv)
{
    const float* W; const float* bb; float* C;
    if (blockIdx.z == 0)      { W = Wq; bb = bq; C = g_q; }
    else if (blockIdx.z == 1) { W = Wk; bb = bk; C = g_k; }
    else                      { W = Wv; bb = bv; C = g_v; }
    gemm_body(x, W, bb, C);
}

__global__ __launch_bounds__(256) void out_kernel(
    const float* __restrict__ Wo, const float* __restrict__ bo,
    float* __restrict__ out)
{
    gemm_body(g_ctx, Wo, bo, out);
}

// ============================================================================
// Flash attention: Br=Bc=64, Dh=64, 256 threads (16x16), online softmax.
// smem: Qt[d][i] (scaled), Kt[d][j], Vs[k][dh] (stride 68), Ps[i][k] (stride 68)
// ============================================================================
#define ATT_SMEM_FLOATS (4096 + 4096 + 64*68 + 64*68)
#define ATT_SMEM_BYTES  (ATT_SMEM_FLOATS * 4)

__global__ __launch_bounds__(256) void attn_kernel()
{
    extern __shared__ float sm[];
    float* Qt = sm;              // 64x64 transposed: Qt[d*64 + i]
    float* Kt = sm + 4096;       // 64x64 transposed: Kt[d*64 + j]
    float* Vs = sm + 8192;       // 64x68 natural:    Vs[k*68 + dh]
    float* Ps = Vs + 64 * 68;    // 64x68:            Ps[i*68 + k]

    const int bh = blockIdx.y;
    const int b  = bh >> 4;
    const int h  = bh & 15;
    const int q0 = blockIdx.x * 64;
    const int tid = threadIdx.x;
    const int ty = tid >> 4;     // 0..15 -> q rows ty*4..ty*4+3
    const int tx = tid & 15;     // 0..15 -> cols  tx*4..tx*4+3

    const float* Qg = g_q + (size_t)(b * SEQ) * DIMN + h * HD;
    const float* Kg = g_k + (size_t)(b * SEQ) * DIMN + h * HD;
    const float* Vg = g_v + (size_t)(b * SEQ) * DIMN + h * HD;

    // load Q tile transposed, fold in 1/sqrt(Dh)
    {
        const int i  = tid & 63;
        const int dc = (tid >> 6) * 16;
        const float* p = Qg + (size_t)(q0 + i) * DIMN + dc;
#pragma unroll
        for (int c = 0; c < 16; c += 4) {
            float4 v = *(const float4*)(p + c);
            Qt[(dc+c+0)*64 + i] = v.x * 0.125f;
            Qt[(dc+c+1)*64 + i] = v.y * 0.125f;
            Qt[(dc+c+2)*64 + i] = v.z * 0.125f;
            Qt[(dc+c+3)*64 + i] = v.w * 0.125f;
        }
    }

    float m[4], l[4];
    u64 o[4][2];
#pragma unroll
    for (int ii = 0; ii < 4; ii++) {
        m[ii] = -1e30f; l[ii] = 0.0f; o[ii][0] = 0ull; o[ii][1] = 0ull;
    }

    for (int kt = 0; kt < SEQ; kt += 64) {
        __syncthreads();   // previous PV done; also makes Qt visible on iter 0
        // K tile transposed (conflict-free scatter: consecutive j per warp)
        {
            const int j  = tid & 63;
            const int dc = (tid >> 6) * 16;
            const float* p = Kg + (size_t)(kt + j) * DIMN + dc;
#pragma unroll
            for (int c = 0; c < 16; c += 4) {
                float4 v = *(const float4*)(p + c);
                Kt[(dc+c+0)*64 + j] = v.x;
                Kt[(dc+c+1)*64 + j] = v.y;
                Kt[(dc+c+2)*64 + j] = v.z;
                Kt[(dc+c+3)*64 + j] = v.w;
            }
        }
        // V tile natural
        {
            const int k  = tid >> 2;
            const int c0 = (tid & 3) * 16;
            const float* p = Vg + (size_t)(kt + k) * DIMN + c0;
#pragma unroll
            for (int c = 0; c < 16; c += 4) {
                float4 v = *(const float4*)(p + c);
                *(float4*)&Vs[k*68 + c0 + c] = v;
            }
        }
        __syncthreads();

        // scores: s[ii][jj] = sum_d Qt[d][ty*4+ii] * Kt[d][tx*4+jj]
        u64 s2[4][2];
#pragma unroll
        for (int ii = 0; ii < 4; ii++) { s2[ii][0] = 0ull; s2[ii][1] = 0ull; }
#pragma unroll 8
        for (int d = 0; d < 64; d++) {
            ulonglong2 kk = *(const ulonglong2*)&Kt[d*64 + tx*4];
            float4 qq = *(const float4*)&Qt[d*64 + ty*4];
            u64 qd;
            qd = pack2(qq.x, qq.x); ffma2(s2[0][0], qd, kk.x); ffma2(s2[0][1], qd, kk.y);
            qd = pack2(qq.y, qq.y); ffma2(s2[1][0], qd, kk.x); ffma2(s2[1][1], qd, kk.y);
            qd = pack2(qq.z, qq.z); ffma2(s2[2][0], qd, kk.x); ffma2(s2[2][1], qd, kk.y);
            qd = pack2(qq.w, qq.w); ffma2(s2[3][0], qd, kk.x); ffma2(s2[3][1], qd, kk.y);
        }

        // online softmax per row (16 tx lanes own one row group; lanes are
        // contiguous 16-lane warp halves, so xor 1/2/4/8 stays in-group)
#pragma unroll
        for (int ii = 0; ii < 4; ii++) {
            float2 a  = unpack2(s2[ii][0]);
            float2 bb = unpack2(s2[ii][1]);
            float rmax = fmaxf(fmaxf(a.x, a.y), fmaxf(bb.x, bb.y));
#pragma unroll
            for (int ofs = 8; ofs > 0; ofs >>= 1)
                rmax = fmaxf(rmax, __shfl_xor_sync(0xffffffffu, rmax, ofs));
            float mn = fmaxf(m[ii], rmax);
            float alpha = __expf(m[ii] - mn);
            m[ii] = mn;
            float p0 = __expf(a.x  - mn);
            float p1 = __expf(a.y  - mn);
            float p2 = __expf(bb.x - mn);
            float p3 = __expf(bb.y - mn);
            float rs = (p0 + p1) + (p2 + p3);
#pragma unroll
            for (int ofs = 8; ofs > 0; ofs >>= 1)
                rs += __shfl_xor_sync(0xffffffffu, rs, ofs);
            l[ii] = l[ii] * alpha + rs;
            u64 av = pack2(alpha, alpha);
            o[ii][0] = mul2(o[ii][0], av);
            o[ii][1] = mul2(o[ii][1], av);
            *(float4*)&Ps[(ty*4 + ii)*68 + tx*4] = make_float4(p0, p1, p2, p3);
        }
        __syncthreads();

        // O += P @ V : o[ii][dh-pairs] over k
#pragma unroll 8
        for (int k = 0; k < 64; k++) {
            ulonglong2 vv = *(const ulonglong2*)&Vs[k*68 + tx*4];
#pragma unroll
            for (int ii = 0; ii < 4; ii++) {
                float pk = Ps[(ty*4 + ii)*68 + k];
                u64 pd = pack2(pk, pk);
                ffma2(o[ii][0], pd, vv.x);
                ffma2(o[ii][1], pd, vv.y);
            }
        }
    }

    // epilogue: ctx[b, q0+i, h*64 + dh] = O / l
    float* Op = g_ctx + (size_t)(b * SEQ + q0) * DIMN + h * HD;
#pragma unroll
    for (int ii = 0; ii < 4; ii++) {
        float inv = 1.0f / l[ii];
        float2 a = unpack2(o[ii][0]);
        float2 c = unpack2(o[ii][1]);
        float4 r = make_float4(a.x * inv, a.y * inv, c.x * inv, c.y * inv);
        *(float4*)(Op + (size_t)(ty*4 + ii) * DIMN + tx*4) = r;
    }
}

// ============================================================================
extern "C" void kernel_launch(void* const* d_in, const int* in_sizes, int n_in,
                              void* d_out, int out_size)
{
    (void)in_sizes; (void)n_in; (void)out_size;
    const float* x  = (const float*)d_in[0];
    const float* Wq = (const float*)d_in[1];
    const float* bq = (const float*)d_in[2];
    const float* Wk = (const float*)d_in[3];
    const float* bk = (const float*)d_in[4];
    const float* Wv = (const float*)d_in[5];
    const float* bv = (const float*)d_in[6];
    const float* Wo = (const float*)d_in[7];
    const float* bo = (const float*)d_in[8];
    float* out = (float*)d_out;

    cudaFuncSetAttribute(attn_kernel,
                         cudaFuncAttributeMaxDynamicSharedMemorySize,
                         ATT_SMEM_BYTES);

    dim3 gqkv(DIMN / 128, NTOK / 128, 3);
    qkv_kernel<<<gqkv, 256>>>(x, Wq, bq, Wk, bk, Wv, bv);

    dim3 gatt(SEQ / 64, BATCH * NH);
    attn_kernel<<<gatt, 256, ATT_SMEM_BYTES>>>();

    dim3 gout(DIMN / 128, NTOK / 128);
    out_kernel<<<gout, 256>>>(Wo, bo, out);
}

// round 11
// speedup vs baseline: 1.0003x; 1.0003x over previous
#include <cuda_runtime.h>

#define DIMN 1024
#define NH   16
#define HD   64
#define BATCH 2
#define SEQ  2048
#define NTOK (BATCH*SEQ)   // 4096

// ---------------- scratch (device globals: allocation-free) ----------------
__device__ float g_q[NTOK * DIMN];
__device__ float g_k[NTOK * DIMN];
__device__ float g_v[NTOK * DIMN];
__device__ float g_ctx[NTOK * DIMN];

typedef unsigned long long u64;

// ---------------- packed f32x2 helpers (sm_100+ PTX) ----------------
__device__ __forceinline__ u64 pack2(float x, float y) {
    u64 r; asm("mov.b64 %0, {%1,%2};" : "=l"(r) : "f"(x), "f"(y)); return r;
}
__device__ __forceinline__ void ffma2(u64 &d, u64 a, u64 b) {
    asm("fma.rn.f32x2 %0, %1, %2, %0;" : "+l"(d) : "l"(a), "l"(b));
}
__device__ __forceinline__ u64 mul2(u64 a, u64 b) {
    u64 r; asm("mul.rn.f32x2 %0, %1, %2;" : "=l"(r) : "l"(a), "l"(b)); return r;
}
__device__ __forceinline__ float2 unpack2(u64 v) {
    float lo, hi; asm("mov.b64 {%0,%1}, %2;" : "=f"(lo), "=f"(hi) : "l"(v));
    float2 r; r.x = lo; r.y = hi; return r;
}

// ============================================================================
// SGEMM body: C[M,1024] = A[M,1024] @ W^T[1024,1024] + bias  (both K-major)
// BM=BN=128, BK=16, 256 threads, 8x8 microtile, f32x2 accumulation.
// ============================================================================
__device__ __forceinline__ void gemm_body(const float* __restrict__ A,
                                          const float* __restrict__ W,
                                          const float* __restrict__ bias,
                                          float* __restrict__ C)
{
    __shared__ float As[16 * 128];
    __shared__ float Bs[16 * 128];

    const int tid = threadIdx.x;
    const int m0 = blockIdx.y * 128;
    const int n0 = blockIdx.x * 128;

    // loaders: thread handles rows (lr, lr+64) at k-offset lk..lk+3 of the tile
    const int lr = tid & 63;
    const int lk = (tid >> 6) << 2;          // 0,4,8,12
    const float* Ap  = A + (size_t)(m0 + lr) * DIMN + lk;
    const float* Ap2 = Ap + (size_t)64 * DIMN;
    const float* Wp  = W + (size_t)(n0 + lr) * DIMN + lk;
    const float* Wp2 = Wp + (size_t)64 * DIMN;

    const int tr = tid >> 4;                 // 0..15 -> rows tr*8..tr*8+7
    const int tc = tid & 15;                 // 0..15 -> cols tc*8..tc*8+7

    u64 acc[8][4];
#pragma unroll
    for (int i = 0; i < 8; i++)
#pragma unroll
        for (int j = 0; j < 4; j++) acc[i][j] = 0ull;

    for (int kt = 0; kt < DIMN; kt += 16) {
        float4 a0 = *(const float4*)(Ap  + kt);
        float4 a1 = *(const float4*)(Ap2 + kt);
        float4 b0 = *(const float4*)(Wp  + kt);
        float4 b1 = *(const float4*)(Wp2 + kt);
        __syncthreads();
        // transposed store: As[k][row] (conflict-free: consecutive lr per warp)
        As[(lk+0)*128 + lr] = a0.x;  As[(lk+1)*128 + lr] = a0.y;
        As[(lk+2)*128 + lr] = a0.z;  As[(lk+3)*128 + lr] = a0.w;
        As[(lk+0)*128 + 64 + lr] = a1.x;  As[(lk+1)*128 + 64 + lr] = a1.y;
        As[(lk+2)*128 + 64 + lr] = a1.z;  As[(lk+3)*128 + 64 + lr] = a1.w;
        Bs[(lk+0)*128 + lr] = b0.x;  Bs[(lk+1)*128 + lr] = b0.y;
        Bs[(lk+2)*128 + lr] = b0.z;  Bs[(lk+3)*128 + lr] = b0.w;
        Bs[(lk+0)*128 + 64 + lr] = b1.x;  Bs[(lk+1)*128 + 64 + lr] = b1.y;
        Bs[(lk+2)*128 + 64 + lr] = b1.z;  Bs[(lk+3)*128 + 64 + lr] = b1.w;
        __syncthreads();

#pragma unroll
        for (int k = 0; k < 16; k++) {
            float4 ra0 = *(const float4*)&As[k*128 + tr*8];
            float4 ra1 = *(const float4*)&As[k*128 + tr*8 + 4];
            ulonglong2 rb0 = *(const ulonglong2*)&Bs[k*128 + tc*8];
            ulonglong2 rb1 = *(const ulonglong2*)&Bs[k*128 + tc*8 + 4];
            const u64 bb0 = rb0.x, bb1 = rb0.y, bb2 = rb1.x, bb3 = rb1.y;
            float av[8] = {ra0.x, ra0.y, ra0.z, ra0.w, ra1.x, ra1.y, ra1.z, ra1.w};
#pragma unroll
            for (int i = 0; i < 8; i++) {
                u64 ad = pack2(av[i], av[i]);
                ffma2(acc[i][0], ad, bb0);
                ffma2(acc[i][1], ad, bb1);
                ffma2(acc[i][2], ad, bb2);
                ffma2(acc[i][3], ad, bb3);
            }
        }
    }

    // epilogue: add bias, write two float4 per row
    const float* bp = bias + n0 + tc * 8;
    float bvv[8];
#pragma unroll
    for (int j = 0; j < 8; j++) bvv[j] = bp[j];
#pragma unroll
    for (int i = 0; i < 8; i++) {
        float* Cp = C + (size_t)(m0 + tr*8 + i) * DIMN + n0 + tc*8;
        float2 v0 = unpack2(acc[i][0]);
        float2 v1 = unpack2(acc[i][1]);
        float2 v2 = unpack2(acc[i][2]);
        float2 v3 = unpack2(acc[i][3]);
        float4 o0 = make_float4(v0.x + bvv[0], v0.y + bvv[1], v1.x + bvv[2], v1.y + bvv[3]);
        float4 o1 = make_float4(v2.x + bvv[4], v2.y + bvv[5], v3.x + bvv[6], v3.y + bvv[7]);
        *(float4*)(Cp)     = o0;
        *(float4*)(Cp + 4) = o1;
    }
}

// QKV: grid.z selects projection -> better L2 reuse of x, one launch.
__global__ __launch_bounds__(256) void qkv_kernel(
    const float* __restrict__ x,
    const float* __restrict__ Wq, const float* __restrict__ bq,
    const float* __restrict__ Wk, const float* __restrict__ bk,
    const float* __restrict__ Wv, const float* __restrict__ bv)
{
    const float* W; const float* bb; float* C;
    if (blockIdx.z == 0)      { W = Wq; bb = bq; C = g_q; }
    else if (blockIdx.z == 1) { W = Wk; bb = bk; C = g_k; }
    else                      { W = Wv; bb = bv; C = g_v; }
    gemm_body(x, W, bb, C);
}

__global__ __launch_bounds__(256) void out_kernel(
    const float* __restrict__ Wo, const float* __restrict__ bo,
    float* __restrict__ out)
{
    gemm_body(g_ctx, Wo, bo, out);
}

// ============================================================================
// Flash attention: Br=Bc=64, Dh=64, 256 threads (16x16), online softmax.
// smem: Qt[d][i] (scaled), Kt[d][j], Vs[k][dh] (stride 68), Ps[i][k] (stride 68)
// ============================================================================
#define ATT_SMEM_FLOATS (4096 + 4096 + 64*68 + 64*68)
#define ATT_SMEM_BYTES  (ATT_SMEM_FLOATS * 4)

__global__ __launch_bounds__(256) void attn_kernel()
{
    extern __shared__ float sm[];
    float* Qt = sm;              // 64x64 transposed: Qt[d*64 + i]
    float* Kt = sm + 4096;       // 64x64 transposed: Kt[d*64 + j]
    float* Vs = sm + 8192;       // 64x68 natural:    Vs[k*68 + dh]
    float* Ps = Vs + 64 * 68;    // 64x68:            Ps[i*68 + k]

    const int bh = blockIdx.y;
    const int b  = bh >> 4;
    const int h  = bh & 15;
    const int q0 = blockIdx.x * 64;
    const int tid = threadIdx.x;
    const int ty = tid >> 4;     // 0..15 -> q rows ty*4..ty*4+3
    const int tx = tid & 15;     // 0..15 -> cols  tx*4..tx*4+3

    const float* Qg = g_q + (size_t)(b * SEQ) * DIMN + h * HD;
    const float* Kg = g_k + (size_t)(b * SEQ) * DIMN + h * HD;
    const float* Vg = g_v + (size_t)(b * SEQ) * DIMN + h * HD;

    // load Q tile transposed, fold in 1/sqrt(Dh)
    {
        const int i  = tid & 63;
        const int dc = (tid >> 6) * 16;
        const float* p = Qg + (size_t)(q0 + i) * DIMN + dc;
#pragma unroll
        for (int c = 0; c < 16; c += 4) {
            float4 v = *(const float4*)(p + c);
            Qt[(dc+c+0)*64 + i] = v.x * 0.125f;
            Qt[(dc+c+1)*64 + i] = v.y * 0.125f;
            Qt[(dc+c+2)*64 + i] = v.z * 0.125f;
            Qt[(dc+c+3)*64 + i] = v.w * 0.125f;
        }
    }

    float m[4], l[4];
    u64 o[4][2];
#pragma unroll
    for (int ii = 0; ii < 4; ii++) {
        m[ii] = -1e30f; l[ii] = 0.0f; o[ii][0] = 0ull; o[ii][1] = 0ull;
    }

    for (int kt = 0; kt < SEQ; kt += 64) {
        __syncthreads();   // previous PV done; also makes Qt visible on iter 0
        // K tile transposed (conflict-free scatter: consecutive j per warp)
        {
            const int j  = tid & 63;
            const int dc = (tid >> 6) * 16;
            const float* p = Kg + (size_t)(kt + j) * DIMN + dc;
#pragma unroll
            for (int c = 0; c < 16; c += 4) {
                float4 v = *(const float4*)(p + c);
                Kt[(dc+c+0)*64 + j] = v.x;
                Kt[(dc+c+1)*64 + j] = v.y;
                Kt[(dc+c+2)*64 + j] = v.z;
                Kt[(dc+c+3)*64 + j] = v.w;
            }
        }
        // V tile natural
        {
            const int k  = tid >> 2;
            const int c0 = (tid & 3) * 16;
            const float* p = Vg + (size_t)(kt + k) * DIMN + c0;
#pragma unroll
            for (int c = 0; c < 16; c += 4) {
                float4 v = *(const float4*)(p + c);
                *(float4*)&Vs[k*68 + c0 + c] = v;
            }
        }
        __syncthreads();

        // scores: s[ii][jj] = sum_d Qt[d][ty*4+ii] * Kt[d][tx*4+jj]
        u64 s2[4][2];
#pragma unroll
        for (int ii = 0; ii < 4; ii++) { s2[ii][0] = 0ull; s2[ii][1] = 0ull; }
#pragma unroll 8
        for (int d = 0; d < 64; d++) {
            ulonglong2 kk = *(const ulonglong2*)&Kt[d*64 + tx*4];
            float4 qq = *(const float4*)&Qt[d*64 + ty*4];
            u64 qd;
            qd = pack2(qq.x, qq.x); ffma2(s2[0][0], qd, kk.x); ffma2(s2[0][1], qd, kk.y);
            qd = pack2(qq.y, qq.y); ffma2(s2[1][0], qd, kk.x); ffma2(s2[1][1], qd, kk.y);
            qd = pack2(qq.z, qq.z); ffma2(s2[2][0], qd, kk.x); ffma2(s2[2][1], qd, kk.y);
            qd = pack2(qq.w, qq.w); ffma2(s2[3][0], qd, kk.x); ffma2(s2[3][1], qd, kk.y);
        }

        // online softmax per row (16 tx lanes own one row group; lanes are
        // contiguous 16-lane warp halves, so xor 1/2/4/8 stays in-group)
#pragma unroll
        for (int ii = 0; ii < 4; ii++) {
            float2 a  = unpack2(s2[ii][0]);
            float2 bb = unpack2(s2[ii][1]);
            float rmax = fmaxf(fmaxf(a.x, a.y), fmaxf(bb.x, bb.y));
#pragma unroll
            for (int ofs = 8; ofs > 0; ofs >>= 1)
                rmax = fmaxf(rmax, __shfl_xor_sync(0xffffffffu, rmax, ofs));
            float mn = fmaxf(m[ii], rmax);
            float alpha = __expf(m[ii] - mn);
            m[ii] = mn;
            float p0 = __expf(a.x  - mn);
            float p1 = __expf(a.y  - mn);
            float p2 = __expf(bb.x - mn);
            float p3 = __expf(bb.y - mn);
            float rs = (p0 + p1) + (p2 + p3);
#pragma unroll
            for (int ofs = 8; ofs > 0; ofs >>= 1)
                rs += __shfl_xor_sync(0xffffffffu, rs, ofs);
            l[ii] = l[ii] * alpha + rs;
            u64 av = pack2(alpha, alpha);
            o[ii][0] = mul2(o[ii][0], av);
            o[ii][1] = mul2(o[ii][1], av);
            *(float4*)&Ps[(ty*4 + ii)*68 + tx*4] = make_float4(p0, p1, p2, p3);
        }
        __syncthreads();

        // O += P @ V : o[ii][dh-pairs] over k
#pragma unroll 8
        for (int k = 0; k < 64; k++) {
            ulonglong2 vv = *(const ulonglong2*)&Vs[k*68 + tx*4];
#pragma unroll
            for (int ii = 0; ii < 4; ii++) {
                float pk = Ps[(ty*4 + ii)*68 + k];
                u64 pd = pack2(pk, pk);
                ffma2(o[ii][0], pd, vv.x);
                ffma2(o[ii][1], pd, vv.y);
            }
        }
    }

    // epilogue: ctx[b, q0+i, h*64 + dh] = O / l
    float* Op = g_ctx + (size_t)(b * SEQ + q0) * DIMN + h * HD;
#pragma unroll
    for (int ii = 0; ii < 4; ii++) {
        float inv = 1.0f / l[ii];
        float2 a = unpack2(o[ii][0]);
        float2 c = unpack2(o[ii][1]);
        float4 r = make_float4(a.x * inv, a.y * inv, c.x * inv, c.y * inv);
        *(float4*)(Op + (size_t)(ty*4 + ii) * DIMN + tx*4) = r;
    }
}

// ============================================================================
extern "C" void kernel_launch(void* const* d_in, const int* in_sizes, int n_in,
                              void* d_out, int out_size)
{
    (void)in_sizes; (void)n_in; (void)out_size;
    const float* x  = (const float*)d_in[0];
    const float* Wq = (const float*)d_in[1];
    const float* bq = (const float*)d_in[2];
    const float* Wk = (const float*)d_in[3];
    const float* bk = (const float*)d_in[4];
    const float* Wv = (const float*)d_in[5];
    const float* bv = (const float*)d_in[6];
    const float* Wo = (const float*)d_in[7];
    const float* bo = (const float*)d_in[8];
    float* out = (float*)d_out;

    cudaFuncSetAttribute(attn_kernel,
                         cudaFuncAttributeMaxDynamicSharedMemorySize,
                         ATT_SMEM_BYTES);

    dim3 gqkv(DIMN / 128, NTOK / 128, 3);
    qkv_kernel<<<gqkv, 256>>>(x, Wq, bq, Wk, bk, Wv, bv);

    dim3 gatt(SEQ / 64, BATCH * NH);
    attn_kernel<<<gatt, 256, ATT_SMEM_BYTES>>>();

    dim3 gout(DIMN / 128, NTOK / 128);
    out_kernel<<<gout, 256>>>(Wo, bo, out);
}

// round 12
// speedup vs baseline: 1.0014x; 1.0011x over previous
#include <cuda_runtime.h>

#define DIMN 1024
#define NH   16
#define HD   64
#define BATCH 2
#define SEQ  2048
#define NTOK (BATCH*SEQ)   // 4096

// ---------------- scratch (device globals: allocation-free) ----------------
__device__ float g_q[NTOK * DIMN];
__device__ float g_k[NTOK * DIMN];
__device__ float g_v[NTOK * DIMN];
__device__ float g_ctx[NTOK * DIMN];

typedef unsigned long long u64;

// ---------------- packed f32x2 helpers (sm_100+ PTX) ----------------
__device__ __forceinline__ u64 pack2(float x, float y) {
    u64 r; asm("mov.b64 %0, {%1,%2};" : "=l"(r) : "f"(x), "f"(y)); return r;
}
__device__ __forceinline__ void ffma2(u64 &d, u64 a, u64 b) {
    asm("fma.rn.f32x2 %0, %1, %2, %0;" : "+l"(d) : "l"(a), "l"(b));
}
__device__ __forceinline__ u64 mul2(u64 a, u64 b) {
    u64 r; asm("mul.rn.f32x2 %0, %1, %2;" : "=l"(r) : "l"(a), "l"(b)); return r;
}
__device__ __forceinline__ float2 unpack2(u64 v) {
    float lo, hi; asm("mov.b64 {%0,%1}, %2;" : "=f"(lo), "=f"(hi) : "l"(v));
    float2 r; r.x = lo; r.y = hi; return r;
}

// ============================================================================
// SGEMM body: C[M,1024] = A[M,1024] @ W^T[1024,1024] + bias  (both K-major)
// BM=BN=128, BK=16, 256 threads, 8x8 microtile, f32x2 accumulation.
// ============================================================================
__device__ __forceinline__ void gemm_body(const float* __restrict__ A,
                                          const float* __restrict__ W,
                                          const float* __restrict__ bias,
                                          float* __restrict__ C)
{
    __shared__ float As[16 * 128];
    __shared__ float Bs[16 * 128];

    const int tid = threadIdx.x;
    const int m0 = blockIdx.y * 128;
    const int n0 = blockIdx.x * 128;

    // loaders: thread handles rows (lr, lr+64) at k-offset lk..lk+3 of the tile
    const int lr = tid & 63;
    const int lk = (tid >> 6) << 2;          // 0,4,8,12
    const float* Ap  = A + (size_t)(m0 + lr) * DIMN + lk;
    const float* Ap2 = Ap + (size_t)64 * DIMN;
    const float* Wp  = W + (size_t)(n0 + lr) * DIMN + lk;
    const float* Wp2 = Wp + (size_t)64 * DIMN;

    const int tr = tid >> 4;                 // 0..15 -> rows tr*8..tr*8+7
    const int tc = tid & 15;                 // 0..15 -> cols tc*8..tc*8+7

    u64 acc[8][4];
#pragma unroll
    for (int i = 0; i < 8; i++)
#pragma unroll
        for (int j = 0; j < 4; j++) acc[i][j] = 0ull;

    for (int kt = 0; kt < DIMN; kt += 16) {
        float4 a0 = *(const float4*)(Ap  + kt);
        float4 a1 = *(const float4*)(Ap2 + kt);
        float4 b0 = *(const float4*)(Wp  + kt);
        float4 b1 = *(const float4*)(Wp2 + kt);
        __syncthreads();
        // transposed store: As[k][row] (conflict-free: consecutive lr per warp)
        As[(lk+0)*128 + lr] = a0.x;  As[(lk+1)*128 + lr] = a0.y;
        As[(lk+2)*128 + lr] = a0.z;  As[(lk+3)*128 + lr] = a0.w;
        As[(lk+0)*128 + 64 + lr] = a1.x;  As[(lk+1)*128 + 64 + lr] = a1.y;
        As[(lk+2)*128 + 64 + lr] = a1.z;  As[(lk+3)*128 + 64 + lr] = a1.w;
        Bs[(lk+0)*128 + lr] = b0.x;  Bs[(lk+1)*128 + lr] = b0.y;
        Bs[(lk+2)*128 + lr] = b0.z;  Bs[(lk+3)*128 + lr] = b0.w;
        Bs[(lk+0)*128 + 64 + lr] = b1.x;  Bs[(lk+1)*128 + 64 + lr] = b1.y;
        Bs[(lk+2)*128 + 64 + lr] = b1.z;  Bs[(lk+3)*128 + 64 + lr] = b1.w;
        __syncthreads();

#pragma unroll
        for (int k = 0; k < 16; k++) {
            float4 ra0 = *(const float4*)&As[k*128 + tr*8];
            float4 ra1 = *(const float4*)&As[k*128 + tr*8 + 4];
            ulonglong2 rb0 = *(const ulonglong2*)&Bs[k*128 + tc*8];
            ulonglong2 rb1 = *(const ulonglong2*)&Bs[k*128 + tc*8 + 4];
            const u64 bb0 = rb0.x, bb1 = rb0.y, bb2 = rb1.x, bb3 = rb1.y;
            float av[8] = {ra0.x, ra0.y, ra0.z, ra0.w, ra1.x, ra1.y, ra1.z, ra1.w};
#pragma unroll
            for (int i = 0; i < 8; i++) {
                u64 ad = pack2(av[i], av[i]);
                ffma2(acc[i][0], ad, bb0);
                ffma2(acc[i][1], ad, bb1);
                ffma2(acc[i][2], ad, bb2);
                ffma2(acc[i][3], ad, bb3);
            }
        }
    }

    // epilogue: add bias, write two float4 per row
    const float* bp = bias + n0 + tc * 8;
    float bvv[8];
#pragma unroll
    for (int j = 0; j < 8; j++) bvv[j] = bp[j];
#pragma unroll
    for (int i = 0; i < 8; i++) {
        float* Cp = C + (size_t)(m0 + tr*8 + i) * DIMN + n0 + tc*8;
        float2 v0 = unpack2(acc[i][0]);
        float2 v1 = unpack2(acc[i][1]);
        float2 v2 = unpack2(acc[i][2]);
        float2 v3 = unpack2(acc[i][3]);
        float4 o0 = make_float4(v0.x + bvv[0], v0.y + bvv[1], v1.x + bvv[2], v1.y + bvv[3]);
        float4 o1 = make_float4(v2.x + bvv[4], v2.y + bvv[5], v3.x + bvv[6], v3.y + bvv[7]);
        *(float4*)(Cp)     = o0;
        *(float4*)(Cp + 4) = o1;
    }
}

// QKV: grid.z selects projection -> better L2 reuse of x, one launch.
__global__ __launch_bounds__(256) void qkv_kernel(
    const float* __restrict__ x,
    const float* __restrict__ Wq, const float* __restrict__ bq,
    const float* __restrict__ Wk, const float* __restrict__ bk,
    const float* __restrict__ Wv, const float* __restrict__ bv)
{
    const float* W; const float* bb; float* C;
    if (blockIdx.z == 0)      { W = Wq; bb = bq; C = g_q; }
    else if (blockIdx.z == 1) { W = Wk; bb = bk; C = g_k; }
    else                      { W = Wv; bb = bv; C = g_v; }
    gemm_body(x, W, bb, C);
}

__global__ __launch_bounds__(256) void out_kernel(
    const float* __restrict__ Wo, const float* __restrict__ bo,
    float* __restrict__ out)
{
    gemm_body(g_ctx, Wo, bo, out);
}

// ============================================================================
// Flash attention: Br=Bc=64, Dh=64, 256 threads (16x16), online softmax.
// smem: Qt[d][i] (scaled), Kt[d][j], Vs[k][dh] (stride 68), Ps[i][k] (stride 68)
// ============================================================================
#define ATT_SMEM_FLOATS (4096 + 4096 + 64*68 + 64*68)
#define ATT_SMEM_BYTES  (ATT_SMEM_FLOATS * 4)

__global__ __launch_bounds__(256) void attn_kernel()
{
    extern __shared__ float sm[];
    float* Qt = sm;              // 64x64 transposed: Qt[d*64 + i]
    float* Kt = sm + 4096;       // 64x64 transposed: Kt[d*64 + j]
    float* Vs = sm + 8192;       // 64x68 natural:    Vs[k*68 + dh]
    float* Ps = Vs + 64 * 68;    // 64x68:            Ps[i*68 + k]

    const int bh = blockIdx.y;
    const int b  = bh >> 4;
    const int h  = bh & 15;
    const int q0 = blockIdx.x * 64;
    const int tid = threadIdx.x;
    const int ty = tid >> 4;     // 0..15 -> q rows ty*4..ty*4+3
    const int tx = tid & 15;     // 0..15 -> cols  tx*4..tx*4+3

    const float* Qg = g_q + (size_t)(b * SEQ) * DIMN + h * HD;
    const float* Kg = g_k + (size_t)(b * SEQ) * DIMN + h * HD;
    const float* Vg = g_v + (size_t)(b * SEQ) * DIMN + h * HD;

    // load Q tile transposed, fold in 1/sqrt(Dh)
    {
        const int i  = tid & 63;
        const int dc = (tid >> 6) * 16;
        const float* p = Qg + (size_t)(q0 + i) * DIMN + dc;
#pragma unroll
        for (int c = 0; c < 16; c += 4) {
            float4 v = *(const float4*)(p + c);
            Qt[(dc+c+0)*64 + i] = v.x * 0.125f;
            Qt[(dc+c+1)*64 + i] = v.y * 0.125f;
            Qt[(dc+c+2)*64 + i] = v.z * 0.125f;
            Qt[(dc+c+3)*64 + i] = v.w * 0.125f;
        }
    }

    float m[4], l[4];
    u64 o[4][2];
#pragma unroll
    for (int ii = 0; ii < 4; ii++) {
        m[ii] = -1e30f; l[ii] = 0.0f; o[ii][0] = 0ull; o[ii][1] = 0ull;
    }

    for (int kt = 0; kt < SEQ; kt += 64) {
        __syncthreads();   // previous PV done; also makes Qt visible on iter 0
        // K tile transposed (conflict-free scatter: consecutive j per warp)
        {
            const int j  = tid & 63;
            const int dc = (tid >> 6) * 16;
            const float* p = Kg + (size_t)(kt + j) * DIMN + dc;
#pragma unroll
            for (int c = 0; c < 16; c += 4) {
                float4 v = *(const float4*)(p + c);
                Kt[(dc+c+0)*64 + j] = v.x;
                Kt[(dc+c+1)*64 + j] = v.y;
                Kt[(dc+c+2)*64 + j] = v.z;
                Kt[(dc+c+3)*64 + j] = v.w;
            }
        }
        // V tile natural
        {
            const int k  = tid >> 2;
            const int c0 = (tid & 3) * 16;
            const float* p = Vg + (size_t)(kt + k) * DIMN + c0;
#pragma unroll
            for (int c = 0; c < 16; c += 4) {
                float4 v = *(const float4*)(p + c);
                *(float4*)&Vs[k*68 + c0 + c] = v;
            }
        }
        __syncthreads();

        // scores: s[ii][jj] = sum_d Qt[d][ty*4+ii] * Kt[d][tx*4+jj]
        u64 s2[4][2];
#pragma unroll
        for (int ii = 0; ii < 4; ii++) { s2[ii][0] = 0ull; s2[ii][1] = 0ull; }
#pragma unroll 8
        for (int d = 0; d < 64; d++) {
            ulonglong2 kk = *(const ulonglong2*)&Kt[d*64 + tx*4];
            float4 qq = *(const float4*)&Qt[d*64 + ty*4];
            u64 qd;
            qd = pack2(qq.x, qq.x); ffma2(s2[0][0], qd, kk.x); ffma2(s2[0][1], qd, kk.y);
            qd = pack2(qq.y, qq.y); ffma2(s2[1][0], qd, kk.x); ffma2(s2[1][1], qd, kk.y);
            qd = pack2(qq.z, qq.z); ffma2(s2[2][0], qd, kk.x); ffma2(s2[2][1], qd, kk.y);
            qd = pack2(qq.w, qq.w); ffma2(s2[3][0], qd, kk.x); ffma2(s2[3][1], qd, kk.y);
        }

        // online softmax per row (16 tx lanes own one row group; lanes are
        // contiguous 16-lane warp halves, so xor 1/2/4/8 stays in-group)
#pragma unroll
        for (int ii = 0; ii < 4; ii++) {
            float2 a  = unpack2(s2[ii][0]);
            float2 bb = unpack2(s2[ii][1]);
            float rmax = fmaxf(fmaxf(a.x, a.y), fmaxf(bb.x, bb.y));
#pragma unroll
            for (int ofs = 8; ofs > 0; ofs >>= 1)
                rmax = fmaxf(rmax, __shfl_xor_sync(0xffffffffu, rmax, ofs));
            float mn = fmaxf(m[ii], rmax);
            float alpha = __expf(m[ii] - mn);
            m[ii] = mn;
            float p0 = __expf(a.x  - mn);
            float p1 = __expf(a.y  - mn);
            float p2 = __expf(bb.x - mn);
            float p3 = __expf(bb.y - mn);
            float rs = (p0 + p1) + (p2 + p3);
#pragma unroll
            for (int ofs = 8; ofs > 0; ofs >>= 1)
                rs += __shfl_xor_sync(0xffffffffu, rs, ofs);
            l[ii] = l[ii] * alpha + rs;
            u64 av = pack2(alpha, alpha);
            o[ii][0] = mul2(o[ii][0], av);
            o[ii][1] = mul2(o[ii][1], av);
            *(float4*)&Ps[(ty*4 + ii)*68 + tx*4] = make_float4(p0, p1, p2, p3);
        }
        __syncthreads();

        // O += P @ V : o[ii][dh-pairs] over k
#pragma unroll 8
        for (int k = 0; k < 64; k++) {
            ulonglong2 vv = *(const ulonglong2*)&Vs[k*68 + tx*4];
#pragma unroll
            for (int ii = 0; ii < 4; ii++) {
                float pk = Ps[(ty*4 + ii)*68 + k];
                u64 pd = pack2(pk, pk);
                ffma2(o[ii][0], pd, vv.x);
                ffma2(o[ii][1], pd, vv.y);
            }
        }
    }

    // epilogue: ctx[b, q0+i, h*64 + dh] = O / l
    float* Op = g_ctx + (size_t)(b * SEQ + q0) * DIMN + h * HD;
#pragma unroll
    for (int ii = 0; ii < 4; ii++) {
        float inv = 1.0f / l[ii];
        float2 a = unpack2(o[ii][0]);
        float2 c = unpack2(o[ii][1]);
        float4 r = make_float4(a.x * inv, a.y * inv, c.x * inv, c.y * inv);
        *(float4*)(Op + (size_t)(ty*4 + ii) * DIMN + tx*4) = r;
    }
}

// ============================================================================
extern "C" void kernel_launch(void* const* d_in, const int* in_sizes, int n_in,
                              void* d_out, int out_size)
{
    (void)in_sizes; (void)n_in; (void)out_size;
    const float* x  = (const float*)d_in[0];
    const float* Wq = (const float*)d_in[1];
    const float* bq = (const float*)d_in[2];
    const float* Wk = (const float*)d_in[3];
    const float* bk = (const float*)d_in[4];
    const float* Wv = (const float*)d_in[5];
    const float* bv = (const float*)d_in[6];
    const float* Wo = (const float*)d_in[7];
    const float* bo = (const float*)d_in[8];
    float* out = (float*)d_out;

    cudaFuncSetAttribute(attn_kernel,
                         cudaFuncAttributeMaxDynamicSharedMemorySize,
                         ATT_SMEM_BYTES);

    dim3 gqkv(DIMN / 128, NTOK / 128, 3);
    qkv_kernel<<<gqkv, 256>>>(x, Wq, bq, Wk, bk, Wv, bv);

    dim3 gatt(SEQ / 64, BATCH * NH);
    attn_kernel<<<gatt, 256, ATT_SMEM_BYTES>>>();

    dim3 gout(DIMN / 128, NTOK / 128);
    out_kernel<<<gout, 256>>>(Wo, bo, out);
}

// round 15
// speedup vs baseline: 1.4999x; 1.4979x over previous
#include <cuda_runtime.h>
#include <cuda_bf16.h>
#include <cstdint>

#define DIMN 1024
#define NH   16
#define HD   64
#define BATCH 2
#define SEQ  2048
#define NTOK (BATCH*SEQ)   // 4096

// ---------------- scratch (device globals: allocation-free) ----------------
__device__ float g_q[NTOK * DIMN];
__device__ float g_k[NTOK * DIMN];
__device__ float g_v[NTOK * DIMN];
__device__ float g_ctx[NTOK * DIMN];
// bf16 hi/lo splits for tensor-core GEMMs
__device__ __nv_bfloat16 g_xh[NTOK * DIMN];
__device__ __nv_bfloat16 g_xl[NTOK * DIMN];
__device__ __nv_bfloat16 g_ch[NTOK * DIMN];
__device__ __nv_bfloat16 g_cl[NTOK * DIMN];
__device__ __nv_bfloat16 g_wh[4 * DIMN * DIMN];
__device__ __nv_bfloat16 g_wl[4 * DIMN * DIMN];

typedef unsigned long long u64;

// ---------------- packed f32x2 helpers (attention kernel) ----------------
__device__ __forceinline__ u64 pack2(float x, float y) {
    u64 r; asm("mov.b64 %0, {%1,%2};" : "=l"(r) : "f"(x), "f"(y)); return r;
}
__device__ __forceinline__ void ffma2(u64 &d, u64 a, u64 b) {
    asm("fma.rn.f32x2 %0, %1, %2, %0;" : "+l"(d) : "l"(a), "l"(b));
}
__device__ __forceinline__ u64 mul2(u64 a, u64 b) {
    u64 r; asm("mul.rn.f32x2 %0, %1, %2;" : "=l"(r) : "l"(a), "l"(b)); return r;
}
__device__ __forceinline__ float2 unpack2(u64 v) {
    float lo, hi; asm("mov.b64 {%0,%1}, %2;" : "=f"(lo), "=f"(hi) : "l"(v));
    float2 r; r.x = lo; r.y = hi; return r;
}

// ---------------- portable (sm_80+) tensor-core helpers ----------------
__device__ __forceinline__ uint32_t s2u(const void* p) {
    return (uint32_t)__cvta_generic_to_shared(p);
}
__device__ __forceinline__ uint32_t swz(uint32_t o) { return o ^ ((o >> 3) & 0x70); }

__device__ __forceinline__ void cp_async16(uint32_t sa, const void* ga) {
    asm volatile("cp.async.cg.shared.global [%0], [%1], 16;" :: "r"(sa), "l"(ga));
}
#define CP_COMMIT() asm volatile("cp.async.commit_group;" ::: "memory")
#define CP_WAIT0()  asm volatile("cp.async.wait_group 0;" ::: "memory")

__device__ __forceinline__ void ldm_x4(uint32_t* r, uint32_t addr) {
    asm volatile("ldmatrix.sync.aligned.m8n8.x4.shared.b16 {%0,%1,%2,%3}, [%4];"
                 : "=r"(r[0]), "=r"(r[1]), "=r"(r[2]), "=r"(r[3]) : "r"(addr));
}
__device__ __forceinline__ void mma_bf16(float* c, const uint32_t* a, const uint32_t* b) {
    asm volatile(
        "mma.sync.aligned.m16n8k16.row.col.f32.bf16.bf16.f32 "
        "{%0,%1,%2,%3}, {%4,%5,%6,%7}, {%8,%9}, {%0,%1,%2,%3};"
        : "+f"(c[0]), "+f"(c[1]), "+f"(c[2]), "+f"(c[3])
        : "r"(a[0]), "r"(a[1]), "r"(a[2]), "r"(a[3]), "r"(b[0]), "r"(b[1]));
}

// ============================================================================
// split kernel: fp32 -> (bf16 hi, bf16 lo)
// sel: 0 = x -> g_xh/g_xl ; 1..4 = W[sel-1] -> g_wh/g_wl ; 5 = g_ctx -> g_ch/g_cl
// ============================================================================
__global__ __launch_bounds__(256) void split_kernel(const float* srcp, int sel, int n4)
{
    const float* src = srcp;
    __nv_bfloat16 *hi, *lo;
    if (sel == 0)      { hi = g_xh; lo = g_xl; }
    else if (sel <= 4) { size_t o = (size_t)(sel - 1) * DIMN * DIMN; hi = g_wh + o; lo = g_wl + o; }
    else               { src = g_ctx; hi = g_ch; lo = g_cl; }

    int i = blockIdx.x * blockDim.x + threadIdx.x;
    if (i >= n4) return;
    float4 v = ((const float4*)src)[i];
    __nv_bfloat16 h0 = __float2bfloat16(v.x);
    __nv_bfloat16 h1 = __float2bfloat16(v.y);
    __nv_bfloat16 h2 = __float2bfloat16(v.z);
    __nv_bfloat16 h3 = __float2bfloat16(v.w);
    __nv_bfloat16 l0 = __float2bfloat16(v.x - __bfloat162float(h0));
    __nv_bfloat16 l1 = __float2bfloat16(v.y - __bfloat162float(h1));
    __nv_bfloat16 l2 = __float2bfloat16(v.z - __bfloat162float(h2));
    __nv_bfloat16 l3 = __float2bfloat16(v.w - __bfloat162float(h3));
    ushort4 H, L;
    H.x = __bfloat16_as_ushort(h0); H.y = __bfloat16_as_ushort(h1);
    H.z = __bfloat16_as_ushort(h2); H.w = __bfloat16_as_ushort(h3);
    L.x = __bfloat16_as_ushort(l0); L.y = __bfloat16_as_ushort(l1);
    L.z = __bfloat16_as_ushort(l2); L.w = __bfloat16_as_ushort(l3);
    *(ushort4*)(hi + 4 * (size_t)i) = H;
    *(ushort4*)(lo + 4 * (size_t)i) = L;
}

// ============================================================================
// mma.sync GEMM: C[4096,1024] = A @ W^T + bias, A/W K-major, bf16x3 split.
// 128x128 CTA tile, 256 threads (8 warps, each 32m x 64n).
// K chunk = 64 bf16 (128B SW128 rows), double-buffered cp.async pipeline.
// Per chunk: 4 k16 steps; per step per warp: ldmatrix frags + 48 HMMA
// (3 split products x 2 m16 x 8 n8).
// ============================================================================
#define GT_STAGE 65536              // 4 tiles x 128 rows x 128 B
#define GT_SMEM  (2 * GT_STAGE)     // 131072 B

__device__ __forceinline__ void load_stage(
    uint32_t st,
    const __nv_bfloat16* __restrict__ Ah, const __nv_bfloat16* __restrict__ Al,
    const __nv_bfloat16* __restrict__ Wh, const __nv_bfloat16* __restrict__ Wl,
    int m0, int n0, int kc, int tid)
{
#pragma unroll
    for (int it = 0; it < 4; it++) {
        int idx = tid + it * 256;
        int row = idx >> 3;
        int ch  = idx & 7;
        uint32_t so = swz((uint32_t)(row * 128 + ch * 16));
        size_t goA = (size_t)(m0 + row) * DIMN + kc + ch * 8;
        size_t goW = (size_t)(n0 + row) * DIMN + kc + ch * 8;
        cp_async16(st +     0 + so, Ah + goA);
        cp_async16(st + 16384 + so, Al + goA);
        cp_async16(st + 32768 + so, Wh + goW);
        cp_async16(st + 49152 + so, Wl + goW);
    }
}

__device__ __forceinline__ void mma_gemm_body(
    const __nv_bfloat16* __restrict__ Ah, const __nv_bfloat16* __restrict__ Al,
    const __nv_bfloat16* __restrict__ Wh, const __nv_bfloat16* __restrict__ Wl,
    const float* __restrict__ bias, float* __restrict__ C)
{
    extern __shared__ __align__(1024) char smem[];
    const uint32_t sb = s2u(smem);
    const int tid  = threadIdx.x;
    const int wid  = tid >> 5;
    const int lane = tid & 31;
    const int m0 = blockIdx.y * 128;
    const int n0 = blockIdx.x * 128;
    const int wm = wid >> 1;     // 0..3 -> m offset wm*32
    const int wn = wid & 1;      // 0..1 -> n offset wn*64

    float acc[2][8][4];
#pragma unroll
    for (int mt = 0; mt < 2; mt++)
#pragma unroll
        for (int nt = 0; nt < 8; nt++)
#pragma unroll
            for (int j = 0; j < 4; j++) acc[mt][nt][j] = 0.0f;

    // prologue: chunk 0 -> stage 0
    load_stage(sb, Ah, Al, Wh, Wl, m0, n0, 0, tid);
    CP_COMMIT();

    // precomputed fragment address components (within a stage)
    const uint32_t a_row  = (uint32_t)(wm * 32 + (lane & 15));          // + mt*16
    const uint32_t a_koff = (uint32_t)((lane >> 4) * 16);               // + ks*32
    const uint32_t b_row  = (uint32_t)(wn * 64 + ((lane >> 4) << 3) + (lane & 7)); // + np*16
    const uint32_t b_koff = (uint32_t)(((lane >> 3) & 1) * 16);         // + ks*32

    for (int c = 0; c < 16; c++) {
        CP_WAIT0();
        __syncthreads();   // chunk c visible to all; prev compute on other stage done
        if (c + 1 < 16) {
            load_stage(sb + ((c + 1) & 1) * GT_STAGE, Ah, Al, Wh, Wl,
                       m0, n0, (c + 1) * 64, tid);
            CP_COMMIT();
        }
        const uint32_t st = sb + (c & 1) * GT_STAGE;

#pragma unroll
        for (int ks = 0; ks < 4; ks++) {
            const uint32_t kb = (uint32_t)(ks * 32);

            uint32_t ah[2][4], al[2][4];
#pragma unroll
            for (int mt = 0; mt < 2; mt++) {
                uint32_t off = swz((a_row + mt * 16) * 128 + kb + a_koff);
                ldm_x4(ah[mt], st + off);
                ldm_x4(al[mt], st + 16384 + off);
            }

            uint32_t bh[8][2], bl[8][2];
#pragma unroll
            for (int np = 0; np < 4; np++) {
                uint32_t off = swz((b_row + np * 16) * 128 + kb + b_koff);
                uint32_t r[4];
                ldm_x4(r, st + 32768 + off);
                bh[2*np][0] = r[0]; bh[2*np][1] = r[1];
                bh[2*np+1][0] = r[2]; bh[2*np+1][1] = r[3];
                ldm_x4(r, st + 49152 + off);
                bl[2*np][0] = r[0]; bl[2*np][1] = r[1];
                bl[2*np+1][0] = r[2]; bl[2*np+1][1] = r[3];
            }

#pragma unroll
            for (int mt = 0; mt < 2; mt++)
#pragma unroll
                for (int nt = 0; nt < 8; nt++) {
                    mma_bf16(acc[mt][nt], ah[mt], bh[nt]);
                    mma_bf16(acc[mt][nt], ah[mt], bl[nt]);
                    mma_bf16(acc[mt][nt], al[mt], bh[nt]);
                }
        }
    }

    // epilogue: D frag (m16n8 f32): lane -> rows (l>>2, l>>2+8), cols (l&3)*2, +1
    const int er = lane >> 2;
    const int ec = (lane & 3) * 2;
#pragma unroll
    for (int mt = 0; mt < 2; mt++) {
        const int r0 = m0 + wm * 32 + mt * 16 + er;
#pragma unroll
        for (int nt = 0; nt < 8; nt++) {
            const int col = n0 + wn * 64 + nt * 8 + ec;
            const float b0 = bias[col], b1 = bias[col + 1];
            float2 v0 = make_float2(acc[mt][nt][0] + b0, acc[mt][nt][1] + b1);
            float2 v1 = make_float2(acc[mt][nt][2] + b0, acc[mt][nt][3] + b1);
            *(float2*)(C + (size_t)r0 * DIMN + col)       = v0;
            *(float2*)(C + (size_t)(r0 + 8) * DIMN + col) = v1;
        }
    }
}

__global__ __launch_bounds__(256) void qkv_mma(
    const float* __restrict__ bq, const float* __restrict__ bk,
    const float* __restrict__ bv)
{
    const size_t wo = (size_t)blockIdx.z * DIMN * DIMN;
    const float* bias; float* C;
    if (blockIdx.z == 0)      { bias = bq; C = g_q; }
    else if (blockIdx.z == 1) { bias = bk; C = g_k; }
    else                      { bias = bv; C = g_v; }
    mma_gemm_body(g_xh, g_xl, g_wh + wo, g_wl + wo, bias, C);
}

__global__ __launch_bounds__(256) void out_mma(
    const float* __restrict__ bo, float* __restrict__ out)
{
    const size_t wo = (size_t)3 * DIMN * DIMN;
    mma_gemm_body(g_ch, g_cl, g_wh + wo, g_wl + wo, bo, out);
}

// ============================================================================
// Flash attention: Br=Bc=64, Dh=64, 256 threads (16x16), online softmax.
// (unchanged — known correct; fp32 f32x2 path)
// ============================================================================
#define ATT_SMEM_FLOATS (4096 + 4096 + 64*68 + 64*68)
#define ATT_SMEM_BYTES  (ATT_SMEM_FLOATS * 4)

__global__ __launch_bounds__(256) void attn_kernel()
{
    extern __shared__ float sm[];
    float* Qt = sm;              // 64x64 transposed: Qt[d*64 + i]
    float* Kt = sm + 4096;       // 64x64 transposed: Kt[d*64 + j]
    float* Vs = sm + 8192;       // 64x68 natural:    Vs[k*68 + dh]
    float* Ps = Vs + 64 * 68;    // 64x68:            Ps[i*68 + k]

    const int bh = blockIdx.y;
    const int b  = bh >> 4;
    const int h  = bh & 15;
    const int q0 = blockIdx.x * 64;
    const int tid = threadIdx.x;
    const int ty = tid >> 4;
    const int tx = tid & 15;

    const float* Qg = g_q + (size_t)(b * SEQ) * DIMN + h * HD;
    const float* Kg = g_k + (size_t)(b * SEQ) * DIMN + h * HD;
    const float* Vg = g_v + (size_t)(b * SEQ) * DIMN + h * HD;

    {
        const int i  = tid & 63;
        const int dc = (tid >> 6) * 16;
        const float* p = Qg + (size_t)(q0 + i) * DIMN + dc;
#pragma unroll
        for (int c = 0; c < 16; c += 4) {
            float4 v = *(const float4*)(p + c);
            Qt[(dc+c+0)*64 + i] = v.x * 0.125f;
            Qt[(dc+c+1)*64 + i] = v.y * 0.125f;
            Qt[(dc+c+2)*64 + i] = v.z * 0.125f;
            Qt[(dc+c+3)*64 + i] = v.w * 0.125f;
        }
    }

    float m[4], l[4];
    u64 o[4][2];
#pragma unroll
    for (int ii = 0; ii < 4; ii++) {
        m[ii] = -1e30f; l[ii] = 0.0f; o[ii][0] = 0ull; o[ii][1] = 0ull;
    }

    for (int kt = 0; kt < SEQ; kt += 64) {
        __syncthreads();
        {
            const int j  = tid & 63;
            const int dc = (tid >> 6) * 16;
            const float* p = Kg + (size_t)(kt + j) * DIMN + dc;
#pragma unroll
            for (int c = 0; c < 16; c += 4) {
                float4 v = *(const float4*)(p + c);
                Kt[(dc+c+0)*64 + j] = v.x;
                Kt[(dc+c+1)*64 + j] = v.y;
                Kt[(dc+c+2)*64 + j] = v.z;
                Kt[(dc+c+3)*64 + j] = v.w;
            }
        }
        {
            const int k  = tid >> 2;
            const int c0 = (tid & 3) * 16;
            const float* p = Vg + (size_t)(kt + k) * DIMN + c0;
#pragma unroll
            for (int c = 0; c < 16; c += 4) {
                float4 v = *(const float4*)(p + c);
                *(float4*)&Vs[k*68 + c0 + c] = v;
            }
        }
        __syncthreads();

        u64 s2[4][2];
#pragma unroll
        for (int ii = 0; ii < 4; ii++) { s2[ii][0] = 0ull; s2[ii][1] = 0ull; }
#pragma unroll 8
        for (int d = 0; d < 64; d++) {
            ulonglong2 kk = *(const ulonglong2*)&Kt[d*64 + tx*4];
            float4 qq = *(const float4*)&Qt[d*64 + ty*4];
            u64 qd;
            qd = pack2(qq.x, qq.x); ffma2(s2[0][0], qd, kk.x); ffma2(s2[0][1], qd, kk.y);
            qd = pack2(qq.y, qq.y); ffma2(s2[1][0], qd, kk.x); ffma2(s2[1][1], qd, kk.y);
            qd = pack2(qq.z, qq.z); ffma2(s2[2][0], qd, kk.x); ffma2(s2[2][1], qd, kk.y);
            qd = pack2(qq.w, qq.w); ffma2(s2[3][0], qd, kk.x); ffma2(s2[3][1], qd, kk.y);
        }

#pragma unroll
        for (int ii = 0; ii < 4; ii++) {
            float2 a  = unpack2(s2[ii][0]);
            float2 bb = unpack2(s2[ii][1]);
            float rmax = fmaxf(fmaxf(a.x, a.y), fmaxf(bb.x, bb.y));
#pragma unroll
            for (int ofs = 8; ofs > 0; ofs >>= 1)
                rmax = fmaxf(rmax, __shfl_xor_sync(0xffffffffu, rmax, ofs));
            float mn = fmaxf(m[ii], rmax);
            float alpha = __expf(m[ii] - mn);
            m[ii] = mn;
            float p0 = __expf(a.x  - mn);
            float p1 = __expf(a.y  - mn);
            float p2 = __expf(bb.x - mn);
            float p3 = __expf(bb.y - mn);
            float rs = (p0 + p1) + (p2 + p3);
#pragma unroll
            for (int ofs = 8; ofs > 0; ofs >>= 1)
                rs += __shfl_xor_sync(0xffffffffu, rs, ofs);
            l[ii] = l[ii] * alpha + rs;
            u64 av = pack2(alpha, alpha);
            o[ii][0] = mul2(o[ii][0], av);
            o[ii][1] = mul2(o[ii][1], av);
            *(float4*)&Ps[(ty*4 + ii)*68 + tx*4] = make_float4(p0, p1, p2, p3);
        }
        __syncthreads();

#pragma unroll 8
        for (int k = 0; k < 64; k++) {
            ulonglong2 vv = *(const ulonglong2*)&Vs[k*68 + tx*4];
#pragma unroll
            for (int ii = 0; ii < 4; ii++) {
                float pk = Ps[(ty*4 + ii)*68 + k];
                u64 pd = pack2(pk, pk);
                ffma2(o[ii][0], pd, vv.x);
                ffma2(o[ii][1], pd, vv.y);
            }
        }
    }

    float* Op = g_ctx + (size_t)(b * SEQ + q0) * DIMN + h * HD;
#pragma unroll
    for (int ii = 0; ii < 4; ii++) {
        float inv = 1.0f / l[ii];
        float2 a = unpack2(o[ii][0]);
        float2 c = unpack2(o[ii][1]);
        float4 r = make_float4(a.x * inv, a.y * inv, c.x * inv, c.y * inv);
        *(float4*)(Op + (size_t)(ty*4 + ii) * DIMN + tx*4) = r;
    }
}

// ============================================================================
extern "C" void kernel_launch(void* const* d_in, const int* in_sizes, int n_in,
                              void* d_out, int out_size)
{
    (void)in_sizes; (void)n_in; (void)out_size;
    const float* x  = (const float*)d_in[0];
    const float* Wq = (const float*)d_in[1];
    const float* bq = (const float*)d_in[2];
    const float* Wk = (const float*)d_in[3];
    const float* bk = (const float*)d_in[4];
    const float* Wv = (const float*)d_in[5];
    const float* bv = (const float*)d_in[6];
    const float* Wo = (const float*)d_in[7];
    const float* bo = (const float*)d_in[8];
    float* out = (float*)d_out;

    cudaFuncSetAttribute(attn_kernel,
                         cudaFuncAttributeMaxDynamicSharedMemorySize, ATT_SMEM_BYTES);
    cudaFuncSetAttribute(qkv_mma,
                         cudaFuncAttributeMaxDynamicSharedMemorySize, GT_SMEM);
    cudaFuncSetAttribute(out_mma,
                         cudaFuncAttributeMaxDynamicSharedMemorySize, GT_SMEM);

    const int n4x = NTOK * DIMN / 4;       // 1M float4
    const int n4w = DIMN * DIMN / 4;       // 256K float4

    split_kernel<<<n4x / 256, 256>>>(x,  0, n4x);
    split_kernel<<<n4w / 256, 256>>>(Wq, 1, n4w);
    split_kernel<<<n4w / 256, 256>>>(Wk, 2, n4w);
    split_kernel<<<n4w / 256, 256>>>(Wv, 3, n4w);
    split_kernel<<<n4w / 256, 256>>>(Wo, 4, n4w);

    dim3 gqkv(DIMN / 128, NTOK / 128, 3);
    qkv_mma<<<gqkv, 256, GT_SMEM>>>(bq, bk, bv);

    dim3 gatt(SEQ / 64, BATCH * NH);
    attn_kernel<<<gatt, 256, ATT_SMEM_BYTES>>>();

    split_kernel<<<n4x / 256, 256>>>(nullptr, 5, n4x);

    dim3 gout(DIMN / 128, NTOK / 128);
    out_mma<<<gout, 256, GT_SMEM>>>(bo, out);
}

// round 16
// speedup vs baseline: 3.1413x; 2.0943x over previous
#include <cuda_runtime.h>
#include <cuda_bf16.h>
#include <cstdint>

#define DIMN 1024
#define NH   16
#define HD   64
#define BATCH 2
#define SEQ  2048
#define NTOK (BATCH*SEQ)   // 4096

// ---------------- scratch (device globals: allocation-free) ----------------
// bf16 hi/lo splits
__device__ __nv_bfloat16 g_xh[NTOK * DIMN];
__device__ __nv_bfloat16 g_xl[NTOK * DIMN];
__device__ __nv_bfloat16 g_qh[NTOK * DIMN];
__device__ __nv_bfloat16 g_ql[NTOK * DIMN];
__device__ __nv_bfloat16 g_kh[NTOK * DIMN];
__device__ __nv_bfloat16 g_kl[NTOK * DIMN];
__device__ __nv_bfloat16 g_vh[NTOK * DIMN];
__device__ __nv_bfloat16 g_vl[NTOK * DIMN];
__device__ __nv_bfloat16 g_ch[NTOK * DIMN];
__device__ __nv_bfloat16 g_cl[NTOK * DIMN];
__device__ __nv_bfloat16 g_wh[4 * DIMN * DIMN];
__device__ __nv_bfloat16 g_wl[4 * DIMN * DIMN];

// ---------------- portable (sm_80+) tensor-core helpers ----------------
__device__ __forceinline__ uint32_t s2u(const void* p) {
    return (uint32_t)__cvta_generic_to_shared(p);
}
__device__ __forceinline__ uint32_t swz(uint32_t o) { return o ^ ((o >> 3) & 0x70); }

__device__ __forceinline__ void cp_async16(uint32_t sa, const void* ga) {
    asm volatile("cp.async.cg.shared.global [%0], [%1], 16;" :: "r"(sa), "l"(ga));
}
#define CP_COMMIT() asm volatile("cp.async.commit_group;" ::: "memory")
#define CP_WAIT0()  asm volatile("cp.async.wait_group 0;" ::: "memory")
#define CP_WAIT1()  asm volatile("cp.async.wait_group 1;" ::: "memory")

__device__ __forceinline__ void ldm_x4(uint32_t* r, uint32_t addr) {
    asm volatile("ldmatrix.sync.aligned.m8n8.x4.shared.b16 {%0,%1,%2,%3}, [%4];"
                 : "=r"(r[0]), "=r"(r[1]), "=r"(r[2]), "=r"(r[3]) : "r"(addr));
}
__device__ __forceinline__ void ldm_x4t(uint32_t* r, uint32_t addr) {
    asm volatile("ldmatrix.sync.aligned.m8n8.x4.trans.shared.b16 {%0,%1,%2,%3}, [%4];"
                 : "=r"(r[0]), "=r"(r[1]), "=r"(r[2]), "=r"(r[3]) : "r"(addr));
}
__device__ __forceinline__ void mma_bf16(float* c, const uint32_t* a, const uint32_t* b) {
    asm volatile(
        "mma.sync.aligned.m16n8k16.row.col.f32.bf16.bf16.f32 "
        "{%0,%1,%2,%3}, {%4,%5,%6,%7}, {%8,%9}, {%0,%1,%2,%3};"
        : "+f"(c[0]), "+f"(c[1]), "+f"(c[2]), "+f"(c[3])
        : "r"(a[0]), "r"(a[1]), "r"(a[2]), "r"(a[3]), "r"(b[0]), "r"(b[1]));
}
// split (x,y) -> packed bf16x2 hi + packed bf16x2 lo (x = lower half / even col)
__device__ __forceinline__ void bsplit2(float x, float y, uint32_t& h, uint32_t& lo) {
    float xh = __bfloat162float(__float2bfloat16(x));
    float yh = __bfloat162float(__float2bfloat16(y));
    asm("cvt.rn.bf16x2.f32 %0, %1, %2;" : "=r"(h)  : "f"(yh), "f"(xh));
    asm("cvt.rn.bf16x2.f32 %0, %1, %2;" : "=r"(lo) : "f"(y - yh), "f"(x - xh));
}

// ============================================================================
// split kernel: fp32 -> (bf16 hi, bf16 lo).  sel 0 = x ; 1..4 = W[sel-1]
// ============================================================================
__global__ __launch_bounds__(256) void split_kernel(const float* src, int sel, int n4)
{
    __nv_bfloat16 *hi, *lo;
    if (sel == 0) { hi = g_xh; lo = g_xl; }
    else          { size_t o = (size_t)(sel - 1) * DIMN * DIMN; hi = g_wh + o; lo = g_wl + o; }

    int i = blockIdx.x * blockDim.x + threadIdx.x;
    if (i >= n4) return;
    float4 v = ((const float4*)src)[i];
    uint32_t h01, l01, h23, l23;
    bsplit2(v.x, v.y, h01, l01);
    bsplit2(v.z, v.w, h23, l23);
    uint2 H = make_uint2(h01, h23), L = make_uint2(l01, l23);
    *(uint2*)(hi + 4 * (size_t)i) = H;
    *(uint2*)(lo + 4 * (size_t)i) = L;
}

// ============================================================================
// mma.sync GEMM: 128x128 CTA tile, 256 threads (8 warps, each 32m x 64n).
// K chunk = 64 bf16 (128B SW128 rows), double-buffered cp.async.
// Epilogue: either fp32 out (Cf) or bf16 hi/lo split out (Ch/Cl) with scale.
// ============================================================================
#define GT_STAGE 65536
#define GT_SMEM  (2 * GT_STAGE)

__device__ __forceinline__ void load_stage(
    uint32_t st,
    const __nv_bfloat16* __restrict__ Ah, const __nv_bfloat16* __restrict__ Al,
    const __nv_bfloat16* __restrict__ Wh, const __nv_bfloat16* __restrict__ Wl,
    int m0, int n0, int kc, int tid)
{
#pragma unroll
    for (int it = 0; it < 4; it++) {
        int idx = tid + it * 256;
        int row = idx >> 3;
        int ch  = idx & 7;
        uint32_t so = swz((uint32_t)(row * 128 + ch * 16));
        size_t goA = (size_t)(m0 + row) * DIMN + kc + ch * 8;
        size_t goW = (size_t)(n0 + row) * DIMN + kc + ch * 8;
        cp_async16(st +     0 + so, Ah + goA);
        cp_async16(st + 16384 + so, Al + goA);
        cp_async16(st + 32768 + so, Wh + goW);
        cp_async16(st + 49152 + so, Wl + goW);
    }
}

__device__ __forceinline__ void mma_gemm_body(
    const __nv_bfloat16* __restrict__ Ah, const __nv_bfloat16* __restrict__ Al,
    const __nv_bfloat16* __restrict__ Wh, const __nv_bfloat16* __restrict__ Wl,
    const float* __restrict__ bias, float* __restrict__ Cf,
    __nv_bfloat16* __restrict__ Ch, __nv_bfloat16* __restrict__ Cl, float scale)
{
    extern __shared__ __align__(1024) char smem[];
    const uint32_t sb = s2u(smem);
    const int tid  = threadIdx.x;
    const int wid  = tid >> 5;
    const int lane = tid & 31;
    const int m0 = blockIdx.y * 128;
    const int n0 = blockIdx.x * 128;
    const int wm = wid >> 1;
    const int wn = wid & 1;

    float acc[2][8][4];
#pragma unroll
    for (int mt = 0; mt < 2; mt++)
#pragma unroll
        for (int nt = 0; nt < 8; nt++)
#pragma unroll
            for (int j = 0; j < 4; j++) acc[mt][nt][j] = 0.0f;

    load_stage(sb, Ah, Al, Wh, Wl, m0, n0, 0, tid);
    CP_COMMIT();

    const uint32_t a_row  = (uint32_t)(wm * 32 + (lane & 15));
    const uint32_t a_koff = (uint32_t)((lane >> 4) * 16);
    const uint32_t b_row  = (uint32_t)(wn * 64 + ((lane >> 4) << 3) + (lane & 7));
    const uint32_t b_koff = (uint32_t)(((lane >> 3) & 1) * 16);

    for (int c = 0; c < 16; c++) {
        CP_WAIT0();
        __syncthreads();
        if (c + 1 < 16) {
            load_stage(sb + ((c + 1) & 1) * GT_STAGE, Ah, Al, Wh, Wl,
                       m0, n0, (c + 1) * 64, tid);
            CP_COMMIT();
        }
        const uint32_t st = sb + (c & 1) * GT_STAGE;

#pragma unroll
        for (int ks = 0; ks < 4; ks++) {
            const uint32_t kb = (uint32_t)(ks * 32);
            uint32_t ah[2][4], al[2][4];
#pragma unroll
            for (int mt = 0; mt < 2; mt++) {
                uint32_t off = swz((a_row + mt * 16) * 128 + kb + a_koff);
                ldm_x4(ah[mt], st + off);
                ldm_x4(al[mt], st + 16384 + off);
            }
            uint32_t bh[8][2], bl[8][2];
#pragma unroll
            for (int np = 0; np < 4; np++) {
                uint32_t off = swz((b_row + np * 16) * 128 + kb + b_koff);
                uint32_t r[4];
                ldm_x4(r, st + 32768 + off);
                bh[2*np][0] = r[0]; bh[2*np][1] = r[1];
                bh[2*np+1][0] = r[2]; bh[2*np+1][1] = r[3];
                ldm_x4(r, st + 49152 + off);
                bl[2*np][0] = r[0]; bl[2*np][1] = r[1];
                bl[2*np+1][0] = r[2]; bl[2*np+1][1] = r[3];
            }
#pragma unroll
            for (int mt = 0; mt < 2; mt++)
#pragma unroll
                for (int nt = 0; nt < 8; nt++) {
                    mma_bf16(acc[mt][nt], ah[mt], bh[nt]);
                    mma_bf16(acc[mt][nt], ah[mt], bl[nt]);
                    mma_bf16(acc[mt][nt], al[mt], bh[nt]);
                }
        }
    }

    const int er = lane >> 2;
    const int ec = (lane & 3) * 2;
#pragma unroll
    for (int mt = 0; mt < 2; mt++) {
        const int r0 = m0 + wm * 32 + mt * 16 + er;
#pragma unroll
        for (int nt = 0; nt < 8; nt++) {
            const int col = n0 + wn * 64 + nt * 8 + ec;
            const float b0 = bias[col], b1 = bias[col + 1];
            float v0 = acc[mt][nt][0] + b0, v1 = acc[mt][nt][1] + b1;
            float v2 = acc[mt][nt][2] + b0, v3 = acc[mt][nt][3] + b1;
            if (Cf) {
                *(float2*)(Cf + (size_t)r0 * DIMN + col)       = make_float2(v0, v1);
                *(float2*)(Cf + (size_t)(r0 + 8) * DIMN + col) = make_float2(v2, v3);
            } else {
                v0 *= scale; v1 *= scale; v2 *= scale; v3 *= scale;
                uint32_t h, lo;
                bsplit2(v0, v1, h, lo);
                *(uint32_t*)(Ch + (size_t)r0 * DIMN + col) = h;
                *(uint32_t*)(Cl + (size_t)r0 * DIMN + col) = lo;
                bsplit2(v2, v3, h, lo);
                *(uint32_t*)(Ch + (size_t)(r0 + 8) * DIMN + col) = h;
                *(uint32_t*)(Cl + (size_t)(r0 + 8) * DIMN + col) = lo;
            }
        }
    }
}

__global__ __launch_bounds__(256) void qkv_mma(
    const float* __restrict__ bq, const float* __restrict__ bk,
    const float* __restrict__ bv)
{
    const size_t wo = (size_t)blockIdx.z * DIMN * DIMN;
    const float* bias; __nv_bfloat16 *Ch, *Cl; float scale = 1.0f;
    if (blockIdx.z == 0)      { bias = bq; Ch = g_qh; Cl = g_ql; scale = 0.125f; }
    else if (blockIdx.z == 1) { bias = bk; Ch = g_kh; Cl = g_kl; }
    else                      { bias = bv; Ch = g_vh; Cl = g_vl; }
    mma_gemm_body(g_xh, g_xl, g_wh + wo, g_wl + wo, bias, nullptr, Ch, Cl, scale);
}

__global__ __launch_bounds__(256) void out_mma(
    const float* __restrict__ bo, float* __restrict__ out)
{
    const size_t wo = (size_t)3 * DIMN * DIMN;
    mma_gemm_body(g_ch, g_cl, g_wh + wo, g_wl + wo, bo, out, nullptr, nullptr, 1.0f);
}

// ============================================================================
// Tensor-core flash attention. Br=128 (8 warps x m16), Bc=64, 256 threads.
// QK^T: Q(hi/lo) x K(hi/lo) bf16x3; softmax fp32; PV: P split in regs x V(hi/lo).
// K consumed [n=key][k=dh] like GEMM-W; V via ldmatrix.trans from [key][dh].
// smem: Qh/Ql 16KB each + 2 stages x (Kh,Kl,Vh,Vl 8KB each) = 96KB.
// ============================================================================
#define AT_ST   32768
#define AT_SMEM (32768 + 2 * 32768)

__device__ __forceinline__ void attn_load_kv(
    uint32_t st, const __nv_bfloat16* Kh, const __nv_bfloat16* Kl,
    const __nv_bfloat16* Vh, const __nv_bfloat16* Vl, int kt, int tid)
{
    const size_t base = (size_t)kt * DIMN;
#pragma unroll
    for (int it = 0; it < 2; it++) {
        int idx = tid + it * 256;
        int row = idx >> 3;
        int ch  = idx & 7;
        uint32_t so = swz((uint32_t)(row * 128 + ch * 16));
        size_t go = base + (size_t)row * DIMN + ch * 8;
        cp_async16(st +     0 + so, Kh + go);
        cp_async16(st +  8192 + so, Kl + go);
        cp_async16(st + 16384 + so, Vh + go);
        cp_async16(st + 24576 + so, Vl + go);
    }
}

__global__ __launch_bounds__(256) void attn_mma()
{
    extern __shared__ __align__(1024) char smem[];
    const uint32_t sb = s2u(smem);
    const int tid  = threadIdx.x;
    const int w    = tid >> 5;
    const int lane = tid & 31;
    const int q0 = blockIdx.x * 128;
    const int bh = blockIdx.y;                 // b*16 + h
    const size_t hoff = (size_t)(bh >> 4) * SEQ * DIMN + (size_t)(bh & 15) * HD;

    const __nv_bfloat16* Qh = g_qh + hoff;
    const __nv_bfloat16* Ql = g_ql + hoff;
    const __nv_bfloat16* Kh = g_kh + hoff;
    const __nv_bfloat16* Kl = g_kl + hoff;
    const __nv_bfloat16* Vh = g_vh + hoff;
    const __nv_bfloat16* Vl = g_vl + hoff;

    // Q tile load (grouped with stage 0)
#pragma unroll
    for (int it = 0; it < 4; it++) {
        int idx = tid + it * 256;
        int row = idx >> 3;
        int ch  = idx & 7;
        uint32_t so = swz((uint32_t)(row * 128 + ch * 16));
        size_t go = (size_t)(q0 + row) * DIMN + ch * 8;
        cp_async16(sb +         so, Qh + go);
        cp_async16(sb + 16384 + so, Ql + go);
    }
    attn_load_kv(sb + AT_ST, Kh, Kl, Vh, Vl, 0, tid);
    CP_COMMIT();
    attn_load_kv(sb + AT_ST + 32768, Kh, Kl, Vh, Vl, 64, tid);
    CP_COMMIT();

    float mx0 = -1e30f, mx1 = -1e30f, ls0 = 0.0f, ls1 = 0.0f;
    float o[8][4];
#pragma unroll
    for (int j = 0; j < 8; j++)
#pragma unroll
        for (int i = 0; i < 4; i++) o[j][i] = 0.0f;

    const uint32_t a_row  = (uint32_t)(w * 16 + (lane & 15));
    const uint32_t a_koff = (uint32_t)((lane >> 4) * 16);
    const uint32_t b_row  = (uint32_t)(((lane >> 4) << 3) + (lane & 7));
    const uint32_t b_koff = (uint32_t)(((lane >> 3) & 1) * 16);
    const uint32_t v_row  = (uint32_t)((lane & 7) + (((lane >> 3) & 1) << 3));
    const uint32_t v_cb   = (uint32_t)((lane >> 4) * 16);

    for (int t = 0; t < 32; t++) {
        CP_WAIT1();
        __syncthreads();
        const uint32_t st = sb + AT_ST + (t & 1) * 32768;

        // ---- scores = Q K^T (pre-scaled Q) ----
        float s[8][4];
#pragma unroll
        for (int j = 0; j < 8; j++)
#pragma unroll
            for (int i = 0; i < 4; i++) s[j][i] = 0.0f;

#pragma unroll
        for (int ks = 0; ks < 4; ks++) {
            const uint32_t kb = (uint32_t)(ks * 32);
            uint32_t qah[4], qal[4];
            {
                uint32_t off = swz(a_row * 128 + kb + a_koff);
                ldm_x4(qah, sb + off);
                ldm_x4(qal, sb + 16384 + off);
            }
#pragma unroll
            for (int np = 0; np < 4; np++) {
                uint32_t off = swz((b_row + np * 16) * 128 + kb + b_koff);
                uint32_t rh[4], rl[4];
                ldm_x4(rh, st + off);
                ldm_x4(rl, st + 8192 + off);
                mma_bf16(s[2*np],   qah, rh);
                mma_bf16(s[2*np],   qah, rl + 0);   // lo b regs r0,r1
                mma_bf16(s[2*np],   qal, rh);
                mma_bf16(s[2*np+1], qah, rh + 2);
                mma_bf16(s[2*np+1], qah, rl + 2);
                mma_bf16(s[2*np+1], qal, rh + 2);
            }
        }

        // ---- online softmax (rows r0 = lane>>2, r1 = r0+8) ----
        float rm0 = -1e30f, rm1 = -1e30f;
#pragma unroll
        for (int j = 0; j < 8; j++) {
            rm0 = fmaxf(rm0, fmaxf(s[j][0], s[j][1]));
            rm1 = fmaxf(rm1, fmaxf(s[j][2], s[j][3]));
        }
#pragma unroll
        for (int ofs = 1; ofs <= 2; ofs <<= 1) {
            rm0 = fmaxf(rm0, __shfl_xor_sync(0xffffffffu, rm0, ofs));
            rm1 = fmaxf(rm1, __shfl_xor_sync(0xffffffffu, rm1, ofs));
        }
        float mn0 = fmaxf(mx0, rm0), mn1 = fmaxf(mx1, rm1);
        float al0 = __expf(mx0 - mn0), al1 = __expf(mx1 - mn1);
        mx0 = mn0; mx1 = mn1;

        float rs0 = 0.0f, rs1 = 0.0f;
#pragma unroll
        for (int j = 0; j < 8; j++) {
            s[j][0] = __expf(s[j][0] - mn0);
            s[j][1] = __expf(s[j][1] - mn0);
            s[j][2] = __expf(s[j][2] - mn1);
            s[j][3] = __expf(s[j][3] - mn1);
            rs0 += s[j][0] + s[j][1];
            rs1 += s[j][2] + s[j][3];
        }
#pragma unroll
        for (int ofs = 1; ofs <= 2; ofs <<= 1) {
            rs0 += __shfl_xor_sync(0xffffffffu, rs0, ofs);
            rs1 += __shfl_xor_sync(0xffffffffu, rs1, ofs);
        }
        ls0 = ls0 * al0 + rs0;
        ls1 = ls1 * al1 + rs1;
#pragma unroll
        for (int j = 0; j < 8; j++) {
            o[j][0] *= al0; o[j][1] *= al0;
            o[j][2] *= al1; o[j][3] *= al1;
        }

        // ---- ctx += P V ----
#pragma unroll
        for (int sk = 0; sk < 4; sk++) {
            uint32_t pah[4], pal[4];
            bsplit2(s[2*sk][0],   s[2*sk][1],   pah[0], pal[0]);
            bsplit2(s[2*sk][2],   s[2*sk][3],   pah[1], pal[1]);
            bsplit2(s[2*sk+1][0], s[2*sk+1][1], pah[2], pal[2]);
            bsplit2(s[2*sk+1][2], s[2*sk+1][3], pah[3], pal[3]);
#pragma unroll
            for (int np = 0; np < 4; np++) {
                uint32_t off = swz((v_row + sk * 16) * 128 + np * 32 + v_cb);
                uint32_t rh[4], rl[4];
                ldm_x4t(rh, st + 16384 + off);
                ldm_x4t(rl, st + 24576 + off);
                mma_bf16(o[2*np],   pah, rh);
                mma_bf16(o[2*np],   pah, rl + 0);
                mma_bf16(o[2*np],   pal, rh);
                mma_bf16(o[2*np+1], pah, rh + 2);
                mma_bf16(o[2*np+1], pah, rl + 2);
                mma_bf16(o[2*np+1], pal, rh + 2);
            }
        }

        __syncthreads();
        if (t + 2 < 32) {
            attn_load_kv(sb + AT_ST + (t & 1) * 32768, Kh, Kl, Vh, Vl,
                         (t + 2) * 64, tid);
            CP_COMMIT();
        }
    }

    // ---- epilogue: ctx hi/lo ----
    const float inv0 = 1.0f / ls0, inv1 = 1.0f / ls1;
    const int r0 = q0 + w * 16 + (lane >> 2);
    const int cb = (bh & 15) * HD + (lane & 3) * 2;
    __nv_bfloat16* Ch = g_ch + (size_t)(bh >> 4) * SEQ * DIMN;
    __nv_bfloat16* Cl = g_cl + (size_t)(bh >> 4) * SEQ * DIMN;
#pragma unroll
    for (int j = 0; j < 8; j++) {
        uint32_t h, lo;
        bsplit2(o[j][0] * inv0, o[j][1] * inv0, h, lo);
        *(uint32_t*)(Ch + (size_t)r0 * DIMN + cb + j * 8) = h;
        *(uint32_t*)(Cl + (size_t)r0 * DIMN + cb + j * 8) = lo;
        bsplit2(o[j][2] * inv1, o[j][3] * inv1, h, lo);
        *(uint32_t*)(Ch + (size_t)(r0 + 8) * DIMN + cb + j * 8) = h;
        *(uint32_t*)(Cl + (size_t)(r0 + 8) * DIMN + cb + j * 8) = lo;
    }
}

// ============================================================================
extern "C" void kernel_launch(void* const* d_in, const int* in_sizes, int n_in,
                              void* d_out, int out_size)
{
    (void)in_sizes; (void)n_in; (void)out_size;
    const float* x  = (const float*)d_in[0];
    const float* Wq = (const float*)d_in[1];
    const float* bq = (const float*)d_in[2];
    const float* Wk = (const float*)d_in[3];
    const float* bk = (const float*)d_in[4];
    const float* Wv = (const float*)d_in[5];
    const float* bv = (const float*)d_in[6];
    const float* Wo = (const float*)d_in[7];
    const float* bo = (const float*)d_in[8];
    float* out = (float*)d_out;

    cudaFuncSetAttribute(qkv_mma,
                         cudaFuncAttributeMaxDynamicSharedMemorySize, GT_SMEM);
    cudaFuncSetAttribute(out_mma,
                         cudaFuncAttributeMaxDynamicSharedMemorySize, GT_SMEM);
    cudaFuncSetAttribute(attn_mma,
                         cudaFuncAttributeMaxDynamicSharedMemorySize, AT_SMEM);

    const int n4x = NTOK * DIMN / 4;
    const int n4w = DIMN * DIMN / 4;

    split_kernel<<<n4x / 256, 256>>>(x,  0, n4x);
    split_kernel<<<n4w / 256, 256>>>(Wq, 1, n4w);
    split_kernel<<<n4w / 256, 256>>>(Wk, 2, n4w);
    split_kernel<<<n4w / 256, 256>>>(Wv, 3, n4w);
    split_kernel<<<n4w / 256, 256>>>(Wo, 4, n4w);

    dim3 gqkv(DIMN / 128, NTOK / 128, 3);
    qkv_mma<<<gqkv, 256, GT_SMEM>>>(bq, bk, bv);

    dim3 gatt(SEQ / 128, BATCH * NH);
    attn_mma<<<gatt, 256, AT_SMEM>>>();

    dim3 gout(DIMN / 128, NTOK / 128);
    out_mma<<<gout, 256, GT_SMEM>>>(bo, out);
}

// round 17
// speedup vs baseline: 3.1493x; 1.0026x over previous
#include <cuda_runtime.h>
#include <cuda_bf16.h>
#include <cstdint>

#define DIMN 1024
#define NH   16
#define HD   64
#define BATCH 2
#define SEQ  2048
#define NTOK (BATCH*SEQ)   // 4096

// ---------------- scratch (device globals: allocation-free) ----------------
// bf16 hi/lo splits
__device__ __nv_bfloat16 g_xh[NTOK * DIMN];
__device__ __nv_bfloat16 g_xl[NTOK * DIMN];
__device__ __nv_bfloat16 g_qh[NTOK * DIMN];
__device__ __nv_bfloat16 g_ql[NTOK * DIMN];
__device__ __nv_bfloat16 g_kh[NTOK * DIMN];
__device__ __nv_bfloat16 g_kl[NTOK * DIMN];
__device__ __nv_bfloat16 g_vh[NTOK * DIMN];
__device__ __nv_bfloat16 g_vl[NTOK * DIMN];
__device__ __nv_bfloat16 g_ch[NTOK * DIMN];
__device__ __nv_bfloat16 g_cl[NTOK * DIMN];
__device__ __nv_bfloat16 g_wh[4 * DIMN * DIMN];
__device__ __nv_bfloat16 g_wl[4 * DIMN * DIMN];

// ---------------- portable (sm_80+) tensor-core helpers ----------------
__device__ __forceinline__ uint32_t s2u(const void* p) {
    return (uint32_t)__cvta_generic_to_shared(p);
}
__device__ __forceinline__ uint32_t swz(uint32_t o) { return o ^ ((o >> 3) & 0x70); }

__device__ __forceinline__ void cp_async16(uint32_t sa, const void* ga) {
    asm volatile("cp.async.cg.shared.global [%0], [%1], 16;" :: "r"(sa), "l"(ga));
}
#define CP_COMMIT() asm volatile("cp.async.commit_group;" ::: "memory")
#define CP_WAIT0()  asm volatile("cp.async.wait_group 0;" ::: "memory")
#define CP_WAIT1()  asm volatile("cp.async.wait_group 1;" ::: "memory")

__device__ __forceinline__ void ldm_x4(uint32_t* r, uint32_t addr) {
    asm volatile("ldmatrix.sync.aligned.m8n8.x4.shared.b16 {%0,%1,%2,%3}, [%4];"
                 : "=r"(r[0]), "=r"(r[1]), "=r"(r[2]), "=r"(r[3]) : "r"(addr));
}
__device__ __forceinline__ void ldm_x4t(uint32_t* r, uint32_t addr) {
    asm volatile("ldmatrix.sync.aligned.m8n8.x4.trans.shared.b16 {%0,%1,%2,%3}, [%4];"
                 : "=r"(r[0]), "=r"(r[1]), "=r"(r[2]), "=r"(r[3]) : "r"(addr));
}
__device__ __forceinline__ void mma_bf16(float* c, const uint32_t* a, const uint32_t* b) {
    asm volatile(
        "mma.sync.aligned.m16n8k16.row.col.f32.bf16.bf16.f32 "
        "{%0,%1,%2,%3}, {%4,%5,%6,%7}, {%8,%9}, {%0,%1,%2,%3};"
        : "+f"(c[0]), "+f"(c[1]), "+f"(c[2]), "+f"(c[3])
        : "r"(a[0]), "r"(a[1]), "r"(a[2]), "r"(a[3]), "r"(b[0]), "r"(b[1]));
}
// split (x,y) -> packed bf16x2 hi + packed bf16x2 lo (x = lower half / even col)
__device__ __forceinline__ void bsplit2(float x, float y, uint32_t& h, uint32_t& lo) {
    float xh = __bfloat162float(__float2bfloat16(x));
    float yh = __bfloat162float(__float2bfloat16(y));
    asm("cvt.rn.bf16x2.f32 %0, %1, %2;" : "=r"(h)  : "f"(yh), "f"(xh));
    asm("cvt.rn.bf16x2.f32 %0, %1, %2;" : "=r"(lo) : "f"(y - yh), "f"(x - xh));
}

// ============================================================================
// split kernel: fp32 -> (bf16 hi, bf16 lo).  sel 0 = x ; 1..4 = W[sel-1]
// ============================================================================
__global__ __launch_bounds__(256) void split_kernel(const float* src, int sel, int n4)
{
    __nv_bfloat16 *hi, *lo;
    if (sel == 0) { hi = g_xh; lo = g_xl; }
    else          { size_t o = (size_t)(sel - 1) * DIMN * DIMN; hi = g_wh + o; lo = g_wl + o; }

    int i = blockIdx.x * blockDim.x + threadIdx.x;
    if (i >= n4) return;
    float4 v = ((const float4*)src)[i];
    uint32_t h01, l01, h23, l23;
    bsplit2(v.x, v.y, h01, l01);
    bsplit2(v.z, v.w, h23, l23);
    uint2 H = make_uint2(h01, h23), L = make_uint2(l01, l23);
    *(uint2*)(hi + 4 * (size_t)i) = H;
    *(uint2*)(lo + 4 * (size_t)i) = L;
}

// ============================================================================
// mma.sync GEMM: 128x128 CTA tile, 256 threads (8 warps, each 32m x 64n).
// K chunk = 64 bf16 (128B SW128 rows), double-buffered cp.async.
// Epilogue: either fp32 out (Cf) or bf16 hi/lo split out (Ch/Cl) with scale.
// ============================================================================
#define GT_STAGE 65536
#define GT_SMEM  (2 * GT_STAGE)

__device__ __forceinline__ void load_stage(
    uint32_t st,
    const __nv_bfloat16* __restrict__ Ah, const __nv_bfloat16* __restrict__ Al,
    const __nv_bfloat16* __restrict__ Wh, const __nv_bfloat16* __restrict__ Wl,
    int m0, int n0, int kc, int tid)
{
#pragma unroll
    for (int it = 0; it < 4; it++) {
        int idx = tid + it * 256;
        int row = idx >> 3;
        int ch  = idx & 7;
        uint32_t so = swz((uint32_t)(row * 128 + ch * 16));
        size_t goA = (size_t)(m0 + row) * DIMN + kc + ch * 8;
        size_t goW = (size_t)(n0 + row) * DIMN + kc + ch * 8;
        cp_async16(st +     0 + so, Ah + goA);
        cp_async16(st + 16384 + so, Al + goA);
        cp_async16(st + 32768 + so, Wh + goW);
        cp_async16(st + 49152 + so, Wl + goW);
    }
}

__device__ __forceinline__ void mma_gemm_body(
    const __nv_bfloat16* __restrict__ Ah, const __nv_bfloat16* __restrict__ Al,
    const __nv_bfloat16* __restrict__ Wh, const __nv_bfloat16* __restrict__ Wl,
    const float* __restrict__ bias, float* __restrict__ Cf,
    __nv_bfloat16* __restrict__ Ch, __nv_bfloat16* __restrict__ Cl, float scale)
{
    extern __shared__ __align__(1024) char smem[];
    const uint32_t sb = s2u(smem);
    const int tid  = threadIdx.x;
    const int wid  = tid >> 5;
    const int lane = tid & 31;
    const int m0 = blockIdx.y * 128;
    const int n0 = blockIdx.x * 128;
    const int wm = wid >> 1;
    const int wn = wid & 1;

    float acc[2][8][4];
#pragma unroll
    for (int mt = 0; mt < 2; mt++)
#pragma unroll
        for (int nt = 0; nt < 8; nt++)
#pragma unroll
            for (int j = 0; j < 4; j++) acc[mt][nt][j] = 0.0f;

    load_stage(sb, Ah, Al, Wh, Wl, m0, n0, 0, tid);
    CP_COMMIT();

    const uint32_t a_row  = (uint32_t)(wm * 32 + (lane & 15));
    const uint32_t a_koff = (uint32_t)((lane >> 4) * 16);
    const uint32_t b_row  = (uint32_t)(wn * 64 + ((lane >> 4) << 3) + (lane & 7));
    const uint32_t b_koff = (uint32_t)(((lane >> 3) & 1) * 16);

    for (int c = 0; c < 16; c++) {
        CP_WAIT0();
        __syncthreads();
        if (c + 1 < 16) {
            load_stage(sb + ((c + 1) & 1) * GT_STAGE, Ah, Al, Wh, Wl,
                       m0, n0, (c + 1) * 64, tid);
            CP_COMMIT();
        }
        const uint32_t st = sb + (c & 1) * GT_STAGE;

#pragma unroll
        for (int ks = 0; ks < 4; ks++) {
            const uint32_t kb = (uint32_t)(ks * 32);
            uint32_t ah[2][4], al[2][4];
#pragma unroll
            for (int mt = 0; mt < 2; mt++) {
                uint32_t off = swz((a_row + mt * 16) * 128 + kb + a_koff);
                ldm_x4(ah[mt], st + off);
                ldm_x4(al[mt], st + 16384 + off);
            }
            uint32_t bh[8][2], bl[8][2];
#pragma unroll
            for (int np = 0; np < 4; np++) {
                uint32_t off = swz((b_row + np * 16) * 128 + kb + b_koff);
                uint32_t r[4];
                ldm_x4(r, st + 32768 + off);
                bh[2*np][0] = r[0]; bh[2*np][1] = r[1];
                bh[2*np+1][0] = r[2]; bh[2*np+1][1] = r[3];
                ldm_x4(r, st + 49152 + off);
                bl[2*np][0] = r[0]; bl[2*np][1] = r[1];
                bl[2*np+1][0] = r[2]; bl[2*np+1][1] = r[3];
            }
#pragma unroll
            for (int mt = 0; mt < 2; mt++)
#pragma unroll
                for (int nt = 0; nt < 8; nt++) {
                    mma_bf16(acc[mt][nt], ah[mt], bh[nt]);
                    mma_bf16(acc[mt][nt], ah[mt], bl[nt]);
                    mma_bf16(acc[mt][nt], al[mt], bh[nt]);
                }
        }
    }

    const int er = lane >> 2;
    const int ec = (lane & 3) * 2;
#pragma unroll
    for (int mt = 0; mt < 2; mt++) {
        const int r0 = m0 + wm * 32 + mt * 16 + er;
#pragma unroll
        for (int nt = 0; nt < 8; nt++) {
            const int col = n0 + wn * 64 + nt * 8 + ec;
            const float b0 = bias[col], b1 = bias[col + 1];
            float v0 = acc[mt][nt][0] + b0, v1 = acc[mt][nt][1] + b1;
            float v2 = acc[mt][nt][2] + b0, v3 = acc[mt][nt][3] + b1;
            if (Cf) {
                *(float2*)(Cf + (size_t)r0 * DIMN + col)       = make_float2(v0, v1);
                *(float2*)(Cf + (size_t)(r0 + 8) * DIMN + col) = make_float2(v2, v3);
            } else {
                v0 *= scale; v1 *= scale; v2 *= scale; v3 *= scale;
                uint32_t h, lo;
                bsplit2(v0, v1, h, lo);
                *(uint32_t*)(Ch + (size_t)r0 * DIMN + col) = h;
                *(uint32_t*)(Cl + (size_t)r0 * DIMN + col) = lo;
                bsplit2(v2, v3, h, lo);
                *(uint32_t*)(Ch + (size_t)(r0 + 8) * DIMN + col) = h;
                *(uint32_t*)(Cl + (size_t)(r0 + 8) * DIMN + col) = lo;
            }
        }
    }
}

__global__ __launch_bounds__(256) void qkv_mma(
    const float* __restrict__ bq, const float* __restrict__ bk,
    const float* __restrict__ bv)
{
    const size_t wo = (size_t)blockIdx.z * DIMN * DIMN;
    const float* bias; __nv_bfloat16 *Ch, *Cl; float scale = 1.0f;
    if (blockIdx.z == 0)      { bias = bq; Ch = g_qh; Cl = g_ql; scale = 0.125f; }
    else if (blockIdx.z == 1) { bias = bk; Ch = g_kh; Cl = g_kl; }
    else                      { bias = bv; Ch = g_vh; Cl = g_vl; }
    mma_gemm_body(g_xh, g_xl, g_wh + wo, g_wl + wo, bias, nullptr, Ch, Cl, scale);
}

__global__ __launch_bounds__(256) void out_mma(
    const float* __restrict__ bo, float* __restrict__ out)
{
    const size_t wo = (size_t)3 * DIMN * DIMN;
    mma_gemm_body(g_ch, g_cl, g_wh + wo, g_wl + wo, bo, out, nullptr, nullptr, 1.0f);
}

// ============================================================================
// Tensor-core flash attention. Br=128 (8 warps x m16), Bc=64, 256 threads.
// QK^T: Q(hi/lo) x K(hi/lo) bf16x3; softmax fp32; PV: P split in regs x V(hi/lo).
// K consumed [n=key][k=dh] like GEMM-W; V via ldmatrix.trans from [key][dh].
// smem: Qh/Ql 16KB each + 2 stages x (Kh,Kl,Vh,Vl 8KB each) = 96KB.
// ============================================================================
#define AT_ST   32768
#define AT_SMEM (32768 + 2 * 32768)

__device__ __forceinline__ void attn_load_kv(
    uint32_t st, const __nv_bfloat16* Kh, const __nv_bfloat16* Kl,
    const __nv_bfloat16* Vh, const __nv_bfloat16* Vl, int kt, int tid)
{
    const size_t base = (size_t)kt * DIMN;
#pragma unroll
    for (int it = 0; it < 2; it++) {
        int idx = tid + it * 256;
        int row = idx >> 3;
        int ch  = idx & 7;
        uint32_t so = swz((uint32_t)(row * 128 + ch * 16));
        size_t go = base + (size_t)row * DIMN + ch * 8;
        cp_async16(st +     0 + so, Kh + go);
        cp_async16(st +  8192 + so, Kl + go);
        cp_async16(st + 16384 + so, Vh + go);
        cp_async16(st + 24576 + so, Vl + go);
    }
}

__global__ __launch_bounds__(256) void attn_mma()
{
    extern __shared__ __align__(1024) char smem[];
    const uint32_t sb = s2u(smem);
    const int tid  = threadIdx.x;
    const int w    = tid >> 5;
    const int lane = tid & 31;
    const int q0 = blockIdx.x * 128;
    const int bh = blockIdx.y;                 // b*16 + h
    const size_t hoff = (size_t)(bh >> 4) * SEQ * DIMN + (size_t)(bh & 15) * HD;

    const __nv_bfloat16* Qh = g_qh + hoff;
    const __nv_bfloat16* Ql = g_ql + hoff;
    const __nv_bfloat16* Kh = g_kh + hoff;
    const __nv_bfloat16* Kl = g_kl + hoff;
    const __nv_bfloat16* Vh = g_vh + hoff;
    const __nv_bfloat16* Vl = g_vl + hoff;

    // Q tile load (grouped with stage 0)
#pragma unroll
    for (int it = 0; it < 4; it++) {
        int idx = tid + it * 256;
        int row = idx >> 3;
        int ch  = idx & 7;
        uint32_t so = swz((uint32_t)(row * 128 + ch * 16));
        size_t go = (size_t)(q0 + row) * DIMN + ch * 8;
        cp_async16(sb +         so, Qh + go);
        cp_async16(sb + 16384 + so, Ql + go);
    }
    attn_load_kv(sb + AT_ST, Kh, Kl, Vh, Vl, 0, tid);
    CP_COMMIT();
    attn_load_kv(sb + AT_ST + 32768, Kh, Kl, Vh, Vl, 64, tid);
    CP_COMMIT();

    float mx0 = -1e30f, mx1 = -1e30f, ls0 = 0.0f, ls1 = 0.0f;
    float o[8][4];
#pragma unroll
    for (int j = 0; j < 8; j++)
#pragma unroll
        for (int i = 0; i < 4; i++) o[j][i] = 0.0f;

    const uint32_t a_row  = (uint32_t)(w * 16 + (lane & 15));
    const uint32_t a_koff = (uint32_t)((lane >> 4) * 16);
    const uint32_t b_row  = (uint32_t)(((lane >> 4) << 3) + (lane & 7));
    const uint32_t b_koff = (uint32_t)(((lane >> 3) & 1) * 16);
    const uint32_t v_row  = (uint32_t)((lane & 7) + (((lane >> 3) & 1) << 3));
    const uint32_t v_cb   = (uint32_t)((lane >> 4) * 16);

    for (int t = 0; t < 32; t++) {
        CP_WAIT1();
        __syncthreads();
        const uint32_t st = sb + AT_ST + (t & 1) * 32768;

        // ---- scores = Q K^T (pre-scaled Q) ----
        float s[8][4];
#pragma unroll
        for (int j = 0; j < 8; j++)
#pragma unroll
            for (int i = 0; i < 4; i++) s[j][i] = 0.0f;

#pragma unroll
        for (int ks = 0; ks < 4; ks++) {
            const uint32_t kb = (uint32_t)(ks * 32);
            uint32_t qah[4], qal[4];
            {
                uint32_t off = swz(a_row * 128 + kb + a_koff);
                ldm_x4(qah, sb + off);
                ldm_x4(qal, sb + 16384 + off);
            }
#pragma unroll
            for (int np = 0; np < 4; np++) {
                uint32_t off = swz((b_row + np * 16) * 128 + kb + b_koff);
                uint32_t rh[4], rl[4];
                ldm_x4(rh, st + off);
                ldm_x4(rl, st + 8192 + off);
                mma_bf16(s[2*np],   qah, rh);
                mma_bf16(s[2*np],   qah, rl + 0);   // lo b regs r0,r1
                mma_bf16(s[2*np],   qal, rh);
                mma_bf16(s[2*np+1], qah, rh + 2);
                mma_bf16(s[2*np+1], qah, rl + 2);
                mma_bf16(s[2*np+1], qal, rh + 2);
            }
        }

        // ---- online softmax (rows r0 = lane>>2, r1 = r0+8) ----
        float rm0 = -1e30f, rm1 = -1e30f;
#pragma unroll
        for (int j = 0; j < 8; j++) {
            rm0 = fmaxf(rm0, fmaxf(s[j][0], s[j][1]));
            rm1 = fmaxf(rm1, fmaxf(s[j][2], s[j][3]));
        }
#pragma unroll
        for (int ofs = 1; ofs <= 2; ofs <<= 1) {
            rm0 = fmaxf(rm0, __shfl_xor_sync(0xffffffffu, rm0, ofs));
            rm1 = fmaxf(rm1, __shfl_xor_sync(0xffffffffu, rm1, ofs));
        }
        float mn0 = fmaxf(mx0, rm0), mn1 = fmaxf(mx1, rm1);
        float al0 = __expf(mx0 - mn0), al1 = __expf(mx1 - mn1);
        mx0 = mn0; mx1 = mn1;

        float rs0 = 0.0f, rs1 = 0.0f;
#pragma unroll
        for (int j = 0; j < 8; j++) {
            s[j][0] = __expf(s[j][0] - mn0);
            s[j][1] = __expf(s[j][1] - mn0);
            s[j][2] = __expf(s[j][2] - mn1);
            s[j][3] = __expf(s[j][3] - mn1);
            rs0 += s[j][0] + s[j][1];
            rs1 += s[j][2] + s[j][3];
        }
#pragma unroll
        for (int ofs = 1; ofs <= 2; ofs <<= 1) {
            rs0 += __shfl_xor_sync(0xffffffffu, rs0, ofs);
            rs1 += __shfl_xor_sync(0xffffffffu, rs1, ofs);
        }
        ls0 = ls0 * al0 + rs0;
        ls1 = ls1 * al1 + rs1;
#pragma unroll
        for (int j = 0; j < 8; j++) {
            o[j][0] *= al0; o[j][1] *= al0;
            o[j][2] *= al1; o[j][3] *= al1;
        }

        // ---- ctx += P V ----
#pragma unroll
        for (int sk = 0; sk < 4; sk++) {
            uint32_t pah[4], pal[4];
            bsplit2(s[2*sk][0],   s[2*sk][1],   pah[0], pal[0]);
            bsplit2(s[2*sk][2],   s[2*sk][3],   pah[1], pal[1]);
            bsplit2(s[2*sk+1][0], s[2*sk+1][1], pah[2], pal[2]);
            bsplit2(s[2*sk+1][2], s[2*sk+1][3], pah[3], pal[3]);
#pragma unroll
            for (int np = 0; np < 4; np++) {
                uint32_t off = swz((v_row + sk * 16) * 128 + np * 32 + v_cb);
                uint32_t rh[4], rl[4];
                ldm_x4t(rh, st + 16384 + off);
                ldm_x4t(rl, st + 24576 + off);
                mma_bf16(o[2*np],   pah, rh);
                mma_bf16(o[2*np],   pah, rl + 0);
                mma_bf16(o[2*np],   pal, rh);
                mma_bf16(o[2*np+1], pah, rh + 2);
                mma_bf16(o[2*np+1], pah, rl + 2);
                mma_bf16(o[2*np+1], pal, rh + 2);
            }
        }

        __syncthreads();
        if (t + 2 < 32) {
            attn_load_kv(sb + AT_ST + (t & 1) * 32768, Kh, Kl, Vh, Vl,
                         (t + 2) * 64, tid);
            CP_COMMIT();
        }
    }

    // ---- epilogue: ctx hi/lo ----
    const float inv0 = 1.0f / ls0, inv1 = 1.0f / ls1;
    const int r0 = q0 + w * 16 + (lane >> 2);
    const int cb = (bh & 15) * HD + (lane & 3) * 2;
    __nv_bfloat16* Ch = g_ch + (size_t)(bh >> 4) * SEQ * DIMN;
    __nv_bfloat16* Cl = g_cl + (size_t)(bh >> 4) * SEQ * DIMN;
#pragma unroll
    for (int j = 0; j < 8; j++) {
        uint32_t h, lo;
        bsplit2(o[j][0] * inv0, o[j][1] * inv0, h, lo);
        *(uint32_t*)(Ch + (size_t)r0 * DIMN + cb + j * 8) = h;
        *(uint32_t*)(Cl + (size_t)r0 * DIMN + cb + j * 8) = lo;
        bsplit2(o[j][2] * inv1, o[j][3] * inv1, h, lo);
        *(uint32_t*)(Ch + (size_t)(r0 + 8) * DIMN + cb + j * 8) = h;
        *(uint32_t*)(Cl + (size_t)(r0 + 8) * DIMN + cb + j * 8) = lo;
    }
}

// ============================================================================
extern "C" void kernel_launch(void* const* d_in, const int* in_sizes, int n_in,
                              void* d_out, int out_size)
{
    (void)in_sizes; (void)n_in; (void)out_size;
    const float* x  = (const float*)d_in[0];
    const float* Wq = (const float*)d_in[1];
    const float* bq = (const float*)d_in[2];
    const float* Wk = (const float*)d_in[3];
    const float* bk = (const float*)d_in[4];
    const float* Wv = (const float*)d_in[5];
    const float* bv = (const float*)d_in[6];
    const float* Wo = (const float*)d_in[7];
    const float* bo = (const float*)d_in[8];
    float* out = (float*)d_out;

    cudaFuncSetAttribute(qkv_mma,
                         cudaFuncAttributeMaxDynamicSharedMemorySize, GT_SMEM);
    cudaFuncSetAttribute(out_mma,
                         cudaFuncAttributeMaxDynamicSharedMemorySize, GT_SMEM);
    cudaFuncSetAttribute(attn_mma,
                         cudaFuncAttributeMaxDynamicSharedMemorySize, AT_SMEM);

    const int n4x = NTOK * DIMN / 4;
    const int n4w = DIMN * DIMN / 4;

    split_kernel<<<n4x / 256, 256>>>(x,  0, n4x);
    split_kernel<<<n4w / 256, 256>>>(Wq, 1, n4w);
    split_kernel<<<n4w / 256, 256>>>(Wk, 2, n4w);
    split_kernel<<<n4w / 256, 256>>>(Wv, 3, n4w);
    split_kernel<<<n4w / 256, 256>>>(Wo, 4, n4w);

    dim3 gqkv(DIMN / 128, NTOK / 128, 3);
    qkv_mma<<<gqkv, 256, GT_SMEM>>>(bq, bk, bv);

    dim3 gatt(SEQ / 128, BATCH * NH);
    attn_mma<<<gatt, 256, AT_SMEM>>>();

    dim3 gout(DIMN / 128, NTOK / 128);
    out_mma<<<gout, 256, GT_SMEM>>>(bo, out);
}